// round 12
// baseline (speedup 1.0000x reference)
#include <cuda_runtime.h>
#include <cuda_fp16.h>
#include <cstdint>
#include <math.h>

#define N_ROWS 400000
#define M_SEG  100000
#define EMB    128
#define CTX    256
#define LAT    256
#define PHSTR  136           // pooled row stride in halves

// smem layout (bytes)
#define OFF_B1S   0          // bias1: 256 f32
#define OFF_B2S   1024       // bias2: 256 f32
#define OFF_AUX   2048       // axseg/axinv 128 x 4B
#define OFF_FRS   2560       // fracs: 128 f32 (gate)
#define OFF_WFR   3072       // wfrac: 256 f32 (gate)
#define OFF_A2    4096       // A2: 128 x 528B = 67584 -> 71680
#define OFF_A10   4096       // A1 buf0 (aliases A2 region)
#define OFF_A11   22528      // A1 buf1
#define OFF_BB0   71680      // B buf0: 36864
#define OFF_BB1   108544     // B buf1: 36864 -> 145408
#define SMEM_TOTAL 145408

#define CHW 18432            // halves per 64-wide B chunk image (256 x 72)

// scratch globals
__device__ __align__(16) __half g_pooled[(size_t)M_SEG * PHSTR];
__device__ float g_counts[M_SEG];
__device__ __align__(16) __half g_ctxpre[(size_t)M_SEG * CTX];   // ctx @ gW1[129:385], fp16
// prepped B chunk images: [chunk][256][72] fp16 RN
__device__ __align__(16) __half g_gwe[2*CHW];   // gate W1 rows 0..127
__device__ __align__(16) __half g_gwc[4*CHW];   // gate W1 rows 129..384
__device__ __align__(16) __half g_gw2[4*CHW];
__device__ __align__(16) __half g_mw1[3*CHW];
__device__ __align__(16) __half g_mw2[4*CHW];

__device__ __forceinline__ uint32_t smem_u32(const void* p) {
    uint32_t a;
    asm("{ .reg .u64 t; cvta.to.shared.u64 t, %1; cvt.u32.u64 %0, t; }" : "=r"(a) : "l"(p));
    return a;
}
#define LDSM4(r0,r1,r2,r3,addr) \
    asm volatile("ldmatrix.sync.aligned.m8n8.x4.shared.b16 {%0,%1,%2,%3}, [%4];" \
        : "=r"(r0),"=r"(r1),"=r"(r2),"=r"(r3) : "r"(addr))
#define MMA(d,a,b0,b1) \
    asm volatile("mma.sync.aligned.m16n8k16.row.col.f32.f16.f16.f32 " \
        "{%0,%1,%2,%3},{%4,%5,%6,%7},{%8,%9},{%0,%1,%2,%3};" \
        : "+f"((d)[0]),"+f"((d)[1]),"+f"((d)[2]),"+f"((d)[3]) \
        : "r"((a)[0]),"r"((a)[1]),"r"((a)[2]),"r"((a)[3]),"r"(b0),"r"(b1))
#define CP16(sa,gp) asm volatile("cp.async.cg.shared.global [%0], [%1], 16;" :: "r"(sa),"l"(gp))
#define CP_COMMIT() asm volatile("cp.async.commit_group;" ::: "memory")
#define CP_WAIT0()  asm volatile("cp.async.wait_group 0;" ::: "memory")
#define STS32(a,v)  asm volatile("st.shared.b32 [%0], %1;" :: "r"(a),"r"(v) : "memory")
#define STSV2(a,x,y) asm volatile("st.shared.v2.b32 [%0], {%1,%2};" :: "r"(a),"r"(x),"r"(y) : "memory")
#define REDH2V4(p,a,b,c,d) \
    asm volatile("red.global.add.noftz.v4.f16x2 [%0], {%1,%2,%3,%4};" \
        :: "l"(p), "r"(a), "r"(b), "r"(c), "r"(d) : "memory")
#define REDH2(p,a) \
    asm volatile("red.global.add.noftz.f16x2 [%0], %1;" :: "l"(p), "r"(a) : "memory")

__device__ __forceinline__ float sp(float x) {
    return fmaxf(x, 0.f) + __logf(1.f + __expf(-fabsf(x)));
}
__device__ __forceinline__ uint32_t pack2h(float a, float b) {
    __half2 h = __floats2half2_rn(a, b);
    return *(uint32_t*)&h;
}

// ---------------------------------------------------------------------------
__global__ void k_zero() {
    long long i = (long long)blockIdx.x * 256 + threadIdx.x;
    const long long P = (long long)M_SEG * PHSTR / 2;
    if (i < P) ((uint32_t*)g_pooled)[i] = 0u;
    else if (i < P + M_SEG) g_counts[i - P] = 0.f;
}

__global__ void k_accum(const float* __restrict__ emb, const float* __restrict__ frac,
                        const int* __restrict__ seg, float* __restrict__ out_frac) {
    int idx = blockIdx.x * 256 + threadIdx.x;
    if (idx >= N_ROWS * 17) return;
    int r = idx / 17;
    int g = idx - r * 17;
    int s = seg[r];
    if (g < 16) {
        const float4* e = (const float4*)&emb[(long long)r * EMB + g * 8];
        float4 a = e[0], b = e[1];
        REDH2V4(&g_pooled[(size_t)s * PHSTR + g * 8],
                pack2h(a.x, a.y), pack2h(a.z, a.w),
                pack2h(b.x, b.y), pack2h(b.z, b.w));
    } else {
        float f = frac[r];
        REDH2(&g_pooled[(size_t)s * PHSTR + 128], pack2h(f, 0.f));
        atomicAdd(&g_counts[s], 1.f);
        if (out_frac) out_frac[r] = f;
    }
}

__global__ void k_prep(const float* __restrict__ W, int mode, int nch, int Kreal, int which) {
    __half* dh;
    if (which == 0)      dh = g_gwe;
    else if (which == 1) dh = g_gwc;
    else if (which == 2) dh = g_gw2;
    else if (which == 3) dh = g_mw1;
    else                 dh = g_mw2;
    int idx = blockIdx.x * 256 + threadIdx.x;
    if (idx >= nch * CHW) return;
    int c = idx / CHW, rem = idx - c * CHW;
    int n = rem / 72, kk = rem - n * 72;
    float v = 0.f;
    if (kk < 64) {
        int kg = c * 64 + kk, sr;
        if (mode == 2) sr = (kg < 256) ? kg + 129 : -1;
        else           sr = (kg < Kreal) ? kg : -1;
        if (sr >= 0) v = W[(long long)sr * 256 + n];
    }
    dh[idx] = __float2half_rn(v);
}

// ---------------------------------------------------------------------------
__device__ __forceinline__ void cp_chunk(uint32_t dst, const __half* src, int c, int tid) {
    const uint4* gp = (const uint4*)src + (long long)c * (CHW / 8);
#pragma unroll
    for (int j = 0; j < 9; j++) {
        int i = tid + j * 256;
        CP16(dst + i * 16, gp + i);
    }
}

// fp16 MMA over one 64-wide K chunk; warp tile 32x128; B stride 144B
__device__ __forceinline__ void mma_chunk(float (&acc)[2][16][4],
                                          uint32_t aBase, int aStride,
                                          uint32_t bBase,
                                          int lane, int m0, int n0w) {
    const int arow = (lane & 7) + ((lane >> 3) & 1) * 8;
    const int brow = (lane & 7) + (lane >> 4) * 8;
    const int bk0  = ((lane >> 3) & 1) * 16;
#pragma unroll
    for (int ks = 0; ks < 4; ks++) {
        uint32_t ah[2][4];
        int akb = ks * 32 + (lane >> 4) * 16;
#pragma unroll
        for (int mi = 0; mi < 2; mi++) {
            uint32_t ra = aBase + (uint32_t)(m0 + mi * 16 + arow) * aStride + akb;
            LDSM4(ah[mi][0], ah[mi][1], ah[mi][2], ah[mi][3], ra);
        }
        int bkb = ks * 32 + bk0;
#pragma unroll
        for (int g = 0; g < 8; g++) {
            uint32_t bh[4];
            uint32_t ro = (uint32_t)(n0w + g * 16 + brow) * 144 + bkb;
            LDSM4(bh[0], bh[1], bh[2], bh[3], bBase + ro);
#pragma unroll
            for (int mi = 0; mi < 2; mi++) {
                MMA(acc[mi][2*g],   ah[mi], bh[0], bh[1]);
                MMA(acc[mi][2*g+1], ah[mi], bh[2], bh[3]);
            }
        }
    }
}

#define CLR_ACC() \
    _Pragma("unroll") for (int i_ = 0; i_ < 2; i_++) \
    _Pragma("unroll") for (int j_ = 0; j_ < 16; j_++) \
    _Pragma("unroll") for (int q_ = 0; q_ < 4; q_++) acc[i_][j_][q_] = 0.f

// ---------------------------------------------------------------------------
// mix: pooled mean -> L1 -> L2 (ctx) -> L3 (ctx @ gWc) -> g_ctxpre (fp16)
__global__ __launch_bounds__(256, 1)
void k_mix(const float* __restrict__ b1v, const float* __restrict__ b2v) {
    extern __shared__ __align__(16) char sm[];
    const uint32_t sb = smem_u32(sm);
    const int tid = threadIdx.x, w = tid >> 5, lane = tid & 31;
    const int m0 = (w & 3) * 32, n0w = (w >> 2) * 128;
    const int rowBase = blockIdx.x * 128;

    float* bias1s = (float*)(sm + OFF_B1S);
    float* bias2s = (float*)(sm + OFF_B2S);
    float* axinv  = (float*)(sm + OFF_AUX);

    bias1s[tid] = b1v[tid];
    bias2s[tid] = b2v[tid];
    if (tid < 128) {
        int gr = rowBase + tid;
        float c = (gr < M_SEG) ? g_counts[gr] : 1.f;
        axinv[tid] = 1.f / fmaxf(c, 1.f);
    }
    __syncthreads();

    const int gr_ = tid >> 1, ghalf = tid & 1;
    const int rg = rowBase + gr_;
    const int kk0 = ghalf * 32;
    auto gather = [&](int c, uint32_t (&ar)[16]) {
#pragma unroll
        for (int i = 0; i < 8; i++) {
            int kk = kk0 + i * 4;
            int k = c * 64 + kk;
            float4 v = make_float4(0.f, 0.f, 0.f, 0.f);
            if (rg < M_SEG) {
                float inv = axinv[gr_];
                if (c < 2) {
                    const __half2* hp = (const __half2*)&g_pooled[(size_t)rg * PHSTR + k];
                    float2 f01 = __half22float2(hp[0]), f23 = __half22float2(hp[1]);
                    v = make_float4(f01.x * inv, f01.y * inv, f23.x * inv, f23.y * inv);
                } else if (kk == 0) {
                    v.x = __half2float(g_pooled[(size_t)rg * PHSTR + 128]) * inv;
                }
            }
            ar[2*i]   = pack2h(v.x, v.y);
            ar[2*i+1] = pack2h(v.z, v.w);
        }
    };
    auto stsA = [&](uint32_t abuf, const uint32_t (&ar)[16]) {
        uint32_t base = abuf + (uint32_t)gr_ * 144 + (uint32_t)kk0 * 2;
#pragma unroll
        for (int i = 0; i < 8; i++)
            STSV2(base + i * 8, ar[2*i], ar[2*i+1]);
    };

    float acc[2][16][4];
    CLR_ACC();
    const int rb = m0 + (lane >> 2);
    const int cb = n0w + (lane & 3) * 2;

    // -------- phase 1: 3 chunks --------
    {
        uint32_t ar[16];
        gather(0, ar); stsA(sb + OFF_A10, ar);
        cp_chunk(sb + OFF_BB0, g_mw1, 0, tid); CP_COMMIT();
    }
    for (int c = 0; c < 3; ++c) {
        uint32_t ar[16];
        if (c + 1 < 3) gather(c + 1, ar);
        CP_WAIT0();
        __syncthreads();
        if (c + 1 < 3) { cp_chunk(sb + (((c+1)&1)?OFF_BB1:OFF_BB0), g_mw1, c+1, tid); CP_COMMIT(); }
        mma_chunk(acc, sb + ((c&1)?OFF_A11:OFF_A10), 144,
                  sb + ((c&1)?OFF_BB1:OFF_BB0), lane, m0, n0w);
        if (c + 1 < 3) stsA(sb + (((c+1)&1)?OFF_A11:OFF_A10), ar);
    }
    __syncthreads();
    cp_chunk(sb + OFF_BB1, g_mw2, 0, tid); CP_COMMIT();   // t=3 -> BB1

    // epi1 -> A2
#pragma unroll
    for (int mi = 0; mi < 2; mi++)
#pragma unroll
        for (int ni = 0; ni < 16; ni++) {
            int col = cb + ni * 8;
            float2 bb = *(float2*)&bias1s[col];
            int row = rb + mi * 16;
            uint32_t ad = sb + OFF_A2 + (uint32_t)row * 528 + (uint32_t)col * 2;
            STS32(ad, pack2h(sp(acc[mi][ni][0]+bb.x), sp(acc[mi][ni][1]+bb.y)));
            STS32(ad + 8*528, pack2h(sp(acc[mi][ni][2]+bb.x), sp(acc[mi][ni][3]+bb.y)));
        }
    CLR_ACC();

    // -------- phase 2: 4 chunks, buf parity (c+1)&1 --------
    for (int c = 0; c < 4; ++c) {
        CP_WAIT0();
        __syncthreads();
        if (c + 1 < 4) { cp_chunk(sb + ((c&1)?OFF_BB1:OFF_BB0), g_mw2, c+1, tid); CP_COMMIT(); }
        else           { cp_chunk(sb + OFF_BB1, g_gwc, 0, tid); CP_COMMIT(); }
        mma_chunk(acc, sb + OFF_A2 + (uint32_t)c * 128, 528,
                  sb + (((c+1)&1)?OFF_BB1:OFF_BB0), lane, m0, n0w);
    }
    __syncthreads();   // A2 rewrite hazard

    // epi2 -> A3 (ctx fp16, same region)
#pragma unroll
    for (int mi = 0; mi < 2; mi++)
#pragma unroll
        for (int ni = 0; ni < 16; ni++) {
            int col = cb + ni * 8;
            float2 bb = *(float2*)&bias2s[col];
            int row = rb + mi * 16;
            uint32_t ad = sb + OFF_A2 + (uint32_t)row * 528 + (uint32_t)col * 2;
            STS32(ad, pack2h(sp(acc[mi][ni][0]+bb.x), sp(acc[mi][ni][1]+bb.y)));
            STS32(ad + 8*528, pack2h(sp(acc[mi][ni][2]+bb.x), sp(acc[mi][ni][3]+bb.y)));
        }
    CLR_ACC();

    // -------- phase 3: 4 chunks --------
    for (int c = 0; c < 4; ++c) {
        CP_WAIT0();
        __syncthreads();
        if (c + 1 < 4) { cp_chunk(sb + ((c&1)?OFF_BB1:OFF_BB0), g_gwc, c+1, tid); CP_COMMIT(); }
        mma_chunk(acc, sb + OFF_A2 + (uint32_t)c * 128, 528,
                  sb + (((c+1)&1)?OFF_BB1:OFF_BB0), lane, m0, n0w);
    }

    // epi3 -> g_ctxpre (fp16, no bias/activation)
#pragma unroll
    for (int mi = 0; mi < 2; mi++)
#pragma unroll
        for (int ni = 0; ni < 16; ni++) {
            int col = cb + ni * 8;
            int gr = rowBase + rb + mi * 16;
            if (gr < M_SEG)
                *(uint32_t*)&g_ctxpre[(size_t)gr * 256 + col] =
                    pack2h(acc[mi][ni][0], acc[mi][ni][1]);
            if (gr + 8 < M_SEG)
                *(uint32_t*)&g_ctxpre[(size_t)(gr+8) * 256 + col] =
                    pack2h(acc[mi][ni][2], acc[mi][ni][3]);
        }
}

// ---------------------------------------------------------------------------
// gate: emb-only L1 (2 chunks) + ctxpre[seg] + frac*w128 -> softplus -> L2 -> out
__global__ __launch_bounds__(256, 1)
void k_gate(const float* __restrict__ emb, const float* __restrict__ frac,
            const int* __restrict__ seg, const float* __restrict__ gW1,
            const float* __restrict__ b1v, const float* __restrict__ b2v,
            float* __restrict__ outp) {
    extern __shared__ __align__(16) char sm[];
    const uint32_t sb = smem_u32(sm);
    const int tid = threadIdx.x, w = tid >> 5, lane = tid & 31;
    const int m0 = (w & 3) * 32, n0w = (w >> 2) * 128;
    const int rowBase = blockIdx.x * 128;

    float* bias1s = (float*)(sm + OFF_B1S);
    float* bias2s = (float*)(sm + OFF_B2S);
    int*   axseg  = (int*)  (sm + OFF_AUX);
    float* fracs  = (float*)(sm + OFF_FRS);
    float* wfrac  = (float*)(sm + OFF_WFR);

    bias1s[tid] = b1v[tid];
    bias2s[tid] = b2v[tid];
    wfrac[tid]  = gW1[128 * 256 + tid];
    if (tid < 128) {
        axseg[tid] = seg[rowBase + tid];
        fracs[tid] = frac[rowBase + tid];
    }
    __syncthreads();

    const int gr_ = tid >> 1, ghalf = tid & 1;
    const int rg = rowBase + gr_;
    const int kk0 = ghalf * 32;
    auto gatherE = [&](int c, uint32_t (&ar)[16]) {
#pragma unroll
        for (int i = 0; i < 8; i++) {
            int kk = kk0 + i * 4;
            float4 v = *(const float4*)&emb[(long long)rg * EMB + c * 64 + kk];
            ar[2*i]   = pack2h(v.x, v.y);
            ar[2*i+1] = pack2h(v.z, v.w);
        }
    };
    auto stsA = [&](uint32_t abuf, const uint32_t (&ar)[16]) {
        uint32_t base = abuf + (uint32_t)gr_ * 144 + (uint32_t)kk0 * 2;
#pragma unroll
        for (int i = 0; i < 8; i++)
            STSV2(base + i * 8, ar[2*i], ar[2*i+1]);
    };

    float acc[2][16][4];
    CLR_ACC();
    const int rb = m0 + (lane >> 2);
    const int cb = n0w + (lane & 3) * 2;

    // -------- phase 1: 2 chunks --------
    {
        uint32_t ar[16];
        gatherE(0, ar); stsA(sb + OFF_A10, ar);
        cp_chunk(sb + OFF_BB0, g_gwe, 0, tid); CP_COMMIT();
    }
    for (int c = 0; c < 2; ++c) {
        uint32_t ar[16];
        if (c + 1 < 2) gatherE(c + 1, ar);
        CP_WAIT0();
        __syncthreads();
        if (c + 1 < 2) { cp_chunk(sb + OFF_BB1, g_gwe, 1, tid); CP_COMMIT(); }
        mma_chunk(acc, sb + ((c&1)?OFF_A11:OFF_A10), 144,
                  sb + ((c&1)?OFF_BB1:OFF_BB0), lane, m0, n0w);
        if (c + 1 < 2) stsA(sb + OFF_A11, ar);
    }
    __syncthreads();
    cp_chunk(sb + OFF_BB0, g_gw2, 0, tid); CP_COMMIT();   // t=2 -> BB0

    // epi1: acc += ctxpre[seg] + frac*wfrac + b1 -> softplus -> A2
    {
        int sgl[4]; float fr[4];
#pragma unroll
        for (int q = 0; q < 4; q++) {
            int row = rb + (q >> 1) * 16 + (q & 1) * 8;
            sgl[q] = axseg[row];
            fr[q]  = fracs[row];
        }
#pragma unroll
        for (int mi = 0; mi < 2; mi++)
#pragma unroll
            for (int ni = 0; ni < 16; ni++) {
                int col = cb + ni * 8;
                float2 bb = *(float2*)&bias1s[col];
                float2 wf = *(float2*)&wfrac[col];
                float2 c0 = __half22float2(*(const __half2*)&g_ctxpre[(size_t)sgl[mi*2]   * 256 + col]);
                float2 c1 = __half22float2(*(const __half2*)&g_ctxpre[(size_t)sgl[mi*2+1] * 256 + col]);
                int row = rb + mi * 16;
                uint32_t ad = sb + OFF_A2 + (uint32_t)row * 528 + (uint32_t)col * 2;
                float y0 = sp(acc[mi][ni][0] + c0.x + fr[mi*2]*wf.x + bb.x);
                float y1 = sp(acc[mi][ni][1] + c0.y + fr[mi*2]*wf.y + bb.y);
                STS32(ad, pack2h(y0, y1));
                float y2 = sp(acc[mi][ni][2] + c1.x + fr[mi*2+1]*wf.x + bb.x);
                float y3 = sp(acc[mi][ni][3] + c1.y + fr[mi*2+1]*wf.y + bb.y);
                STS32(ad + 8*528, pack2h(y2, y3));
            }
    }
    CLR_ACC();

    // -------- phase 2: 4 chunks, buf parity c&1 --------
    for (int c = 0; c < 4; ++c) {
        CP_WAIT0();
        __syncthreads();
        if (c + 1 < 4) { cp_chunk(sb + (((c+1)&1)?OFF_BB1:OFF_BB0), g_gw2, c+1, tid); CP_COMMIT(); }
        mma_chunk(acc, sb + OFF_A2 + (uint32_t)c * 128, 528,
                  sb + ((c&1)?OFF_BB1:OFF_BB0), lane, m0, n0w);
    }

    // epi2 -> out
#pragma unroll
    for (int mi = 0; mi < 2; mi++)
#pragma unroll
        for (int ni = 0; ni < 16; ni++) {
            int col = cb + ni * 8;
            float2 bb = *(float2*)&bias2s[col];
            int gr = rowBase + rb + mi * 16;
            *(float2*)&outp[(long long)gr * 256 + col] =
                make_float2(sp(acc[mi][ni][0]+bb.x), sp(acc[mi][ni][1]+bb.y));
            *(float2*)&outp[(long long)(gr+8) * 256 + col] =
                make_float2(sp(acc[mi][ni][2]+bb.x), sp(acc[mi][ni][3]+bb.y));
        }
}

// ---------------------------------------------------------------------------
extern "C" void kernel_launch(void* const* d_in, const int* in_sizes, int n_in,
                              void* d_out, int out_size) {
    const float* emb  = (const float*)d_in[0];
    const float* frac = (const float*)d_in[1];
    const int*   seg  = (const int*)  d_in[2];
    const float* iW1  = (const float*)d_in[3];
    const float* ib1  = (const float*)d_in[4];
    const float* iW2  = (const float*)d_in[5];
    const float* ib2  = (const float*)d_in[6];
    const float* gW1  = (const float*)d_in[7];
    const float* gb1  = (const float*)d_in[8];
    const float* gW2  = (const float*)d_in[9];
    const float* gb2  = (const float*)d_in[10];
    float* out = (float*)d_out;

    cudaFuncSetAttribute(k_mix,  cudaFuncAttributeMaxDynamicSharedMemorySize, SMEM_TOTAL);
    cudaFuncSetAttribute(k_gate, cudaFuncAttributeMaxDynamicSharedMemorySize, SMEM_TOTAL);

    k_prep<<<(2*CHW + 255)/256, 256>>>(gW1, 0, 2, 128, 0);   // g_gwe
    k_prep<<<(4*CHW + 255)/256, 256>>>(gW1, 2, 4, 256, 1);   // g_gwc
    k_prep<<<(4*CHW + 255)/256, 256>>>(gW2, 0, 4, 256, 2);   // g_gw2
    k_prep<<<(3*CHW + 255)/256, 256>>>(iW1, 0, 3, 129, 3);   // g_mw1
    k_prep<<<(4*CHW + 255)/256, 256>>>(iW2, 0, 4, 256, 4);   // g_mw2

    long long totz = (long long)M_SEG * PHSTR / 2 + M_SEG;
    k_zero<<<(unsigned)((totz + 255)/256), 256>>>();

    float* out_frac = nullptr;
    if ((long long)out_size >= (long long)N_ROWS * (LAT + 1))
        out_frac = out + (size_t)N_ROWS * LAT;
    long long tota = (long long)N_ROWS * 17;
    k_accum<<<(unsigned)((tota + 255)/256), 256>>>(emb, frac, seg, out_frac);

    k_mix<<<(M_SEG + 127)/128, 256, SMEM_TOTAL>>>(ib1, ib2);
    k_gate<<<N_ROWS / 128, 256, SMEM_TOTAL>>>(emb, frac, seg, gW1, gb1, gb2, out);
}

// round 13
// speedup vs baseline: 1.2968x; 1.2968x over previous
#include <cuda_runtime.h>
#include <cuda_fp16.h>
#include <cstdint>
#include <math.h>

#define N_ROWS 400000
#define M_SEG  100000
#define EMB    128
#define CTX    256
#define LAT    256
#define PHSTR  136           // pooled row stride in halves

// chunk geometry: 128 K-cols per chunk, B/A1 row stride 136 halves (272B)
#define CHW 34816            // halves per chunk image (256 x 136)
#define ASTR1 272
#define ASTR2 528

// smem layout (bytes)
#define OFF_B1S   0          // bias1: 256 f32
#define OFF_B2S   1024       // bias2: 256 f32
#define OFF_AUX   2048       // axseg/axinv: 128 x 4B
#define OFF_FRS   2560       // per-row scalar (frac / pooled-frac-mean): 128 f32
#define OFF_WFR   3072       // rank-1 weight row: 256 f32
#define OFF_A2    4096       // A2: 128 x 528B = 67584
#define OFF_A10   4096       // A1 buf0 (aliases A2): 34816
#define OFF_A11   38912      // A1 buf1: 34816 -> 73728
#define OFF_BB0   73728      // B buf0: 69632 -> 143360
#define OFF_BB1   143360     // B buf1: 69632 -> 212992
#define SMEM_TOTAL 212992

// scratch globals
__device__ __align__(16) __half g_pooled[(size_t)M_SEG * PHSTR];
__device__ float g_counts[M_SEG];
__device__ float g_ctxpre[(size_t)M_SEG * CTX];   // ctx @ gW1[129:385], fp32
// prepped B chunk images: [chunk][256][136] fp16 RN (128 data + 8 pad)
__device__ __align__(16) __half g_gwe[1*CHW];   // gate W1 rows 0..127
__device__ __align__(16) __half g_gwc[2*CHW];   // gate W1 rows 129..384
__device__ __align__(16) __half g_gw2[2*CHW];
__device__ __align__(16) __half g_mw1[1*CHW];   // iW1 rows 0..127 (row128 -> epilogue)
__device__ __align__(16) __half g_mw2[2*CHW];

__device__ __forceinline__ uint32_t smem_u32(const void* p) {
    uint32_t a;
    asm("{ .reg .u64 t; cvta.to.shared.u64 t, %1; cvt.u32.u64 %0, t; }" : "=r"(a) : "l"(p));
    return a;
}
#define LDSM4(r0,r1,r2,r3,addr) \
    asm volatile("ldmatrix.sync.aligned.m8n8.x4.shared.b16 {%0,%1,%2,%3}, [%4];" \
        : "=r"(r0),"=r"(r1),"=r"(r2),"=r"(r3) : "r"(addr))
#define MMA(d,a,b0,b1) \
    asm volatile("mma.sync.aligned.m16n8k16.row.col.f32.f16.f16.f32 " \
        "{%0,%1,%2,%3},{%4,%5,%6,%7},{%8,%9},{%0,%1,%2,%3};" \
        : "+f"((d)[0]),"+f"((d)[1]),"+f"((d)[2]),"+f"((d)[3]) \
        : "r"((a)[0]),"r"((a)[1]),"r"((a)[2]),"r"((a)[3]),"r"(b0),"r"(b1))
#define CP16(sa,gp) asm volatile("cp.async.cg.shared.global [%0], [%1], 16;" :: "r"(sa),"l"(gp))
#define CP_COMMIT() asm volatile("cp.async.commit_group;" ::: "memory")
#define CP_WAIT0()  asm volatile("cp.async.wait_group 0;" ::: "memory")
#define STS32(a,v)  asm volatile("st.shared.b32 [%0], %1;" :: "r"(a),"r"(v) : "memory")
#define STSV2(a,x,y) asm volatile("st.shared.v2.b32 [%0], {%1,%2};" :: "r"(a),"r"(x),"r"(y) : "memory")
#define REDH2V4(p,a,b,c,d) \
    asm volatile("red.global.add.noftz.v4.f16x2 [%0], {%1,%2,%3,%4};" \
        :: "l"(p), "r"(a), "r"(b), "r"(c), "r"(d) : "memory")
#define REDH2(p,a) \
    asm volatile("red.global.add.noftz.f16x2 [%0], %1;" :: "l"(p), "r"(a) : "memory")

__device__ __forceinline__ float sp(float x) {
    return fmaxf(x, 0.f) + __logf(1.f + __expf(-fabsf(x)));
}
__device__ __forceinline__ uint32_t pack2h(float a, float b) {
    __half2 h = __floats2half2_rn(a, b);
    return *(uint32_t*)&h;
}

// ---------------------------------------------------------------------------
__global__ void k_zero() {
    long long i = (long long)blockIdx.x * 256 + threadIdx.x;
    const long long P = (long long)M_SEG * PHSTR / 2;
    if (i < P) ((uint32_t*)g_pooled)[i] = 0u;
    else if (i < P + M_SEG) g_counts[i - P] = 0.f;
}

__global__ void k_accum(const float* __restrict__ emb, const float* __restrict__ frac,
                        const int* __restrict__ seg, float* __restrict__ out_frac) {
    int idx = blockIdx.x * 256 + threadIdx.x;
    if (idx >= N_ROWS * 17) return;
    int r = idx / 17;
    int g = idx - r * 17;
    int s = seg[r];
    if (g < 16) {
        const float4* e = (const float4*)&emb[(long long)r * EMB + g * 8];
        float4 a = e[0], b = e[1];
        REDH2V4(&g_pooled[(size_t)s * PHSTR + g * 8],
                pack2h(a.x, a.y), pack2h(a.z, a.w),
                pack2h(b.x, b.y), pack2h(b.z, b.w));
    } else {
        float f = frac[r];
        REDH2(&g_pooled[(size_t)s * PHSTR + 128], pack2h(f, 0.f));
        atomicAdd(&g_counts[s], 1.f);
        if (out_frac) out_frac[r] = f;
    }
}

// prep: W -> chunk images [c][n][136] fp16 RN (128 data + 8 pad)
// mode 0: rows c*128+kk (< Kreal); mode 2: rows c*128+kk+129 (< 256 data rows)
__global__ void k_prep(const float* __restrict__ W, int mode, int nch, int Kreal, int which) {
    __half* dh;
    if (which == 0)      dh = g_gwe;
    else if (which == 1) dh = g_gwc;
    else if (which == 2) dh = g_gw2;
    else if (which == 3) dh = g_mw1;
    else                 dh = g_mw2;
    int idx = blockIdx.x * 256 + threadIdx.x;
    if (idx >= nch * CHW) return;
    int c = idx / CHW, rem = idx - c * CHW;
    int n = rem / 136, kk = rem - n * 136;
    float v = 0.f;
    if (kk < 128) {
        int kg = c * 128 + kk, sr;
        if (mode == 2) sr = (kg < 256) ? kg + 129 : -1;
        else           sr = (kg < Kreal) ? kg : -1;
        if (sr >= 0) v = W[(long long)sr * 256 + n];
    }
    dh[idx] = __float2half_rn(v);
}

// ---------------------------------------------------------------------------
__device__ __forceinline__ void cp_chunk(uint32_t dst, const __half* src, int c, int tid) {
    const uint4* gp = (const uint4*)src + (long long)c * (CHW / 8);
#pragma unroll
    for (int j = 0; j < 17; j++) {
        int i = tid + j * 256;
        CP16(dst + i * 16, gp + i);
    }
}

// fp16 MMA over one 128-wide K chunk; warp tile 32x128; B stride 272B
__device__ __forceinline__ void mma_chunk(float (&acc)[2][16][4],
                                          uint32_t aBase, int aStride,
                                          uint32_t bBase,
                                          int lane, int m0, int n0w) {
    const int arow = (lane & 7) + ((lane >> 3) & 1) * 8;
    const int brow = (lane & 7) + (lane >> 4) * 8;
    const int bk0  = ((lane >> 3) & 1) * 16;
#pragma unroll
    for (int ks = 0; ks < 8; ks++) {
        uint32_t ah[2][4];
        int akb = ks * 32 + (lane >> 4) * 16;
#pragma unroll
        for (int mi = 0; mi < 2; mi++) {
            uint32_t ra = aBase + (uint32_t)(m0 + mi * 16 + arow) * aStride + akb;
            LDSM4(ah[mi][0], ah[mi][1], ah[mi][2], ah[mi][3], ra);
        }
        int bkb = ks * 32 + bk0;
#pragma unroll
        for (int g = 0; g < 8; g++) {
            uint32_t bh[4];
            uint32_t ro = (uint32_t)(n0w + g * 16 + brow) * 272 + bkb;
            LDSM4(bh[0], bh[1], bh[2], bh[3], bBase + ro);
#pragma unroll
            for (int mi = 0; mi < 2; mi++) {
                MMA(acc[mi][2*g],   ah[mi], bh[0], bh[1]);
                MMA(acc[mi][2*g+1], ah[mi], bh[2], bh[3]);
            }
        }
    }
}

#define CLR_ACC() \
    _Pragma("unroll") for (int i_ = 0; i_ < 2; i_++) \
    _Pragma("unroll") for (int j_ = 0; j_ < 16; j_++) \
    _Pragma("unroll") for (int q_ = 0; q_ < 4; q_++) acc[i_][j_][q_] = 0.f

// ---------------------------------------------------------------------------
// mix: pooled mean (128 cols, 1 chunk) + frac rank-1 epi -> L1 -> L2 (ctx)
//      -> L3 (ctx @ gWc) -> g_ctxpre (fp32)
__global__ __launch_bounds__(256, 1)
void k_mix(const float* __restrict__ iW1,
           const float* __restrict__ b1v, const float* __restrict__ b2v) {
    extern __shared__ __align__(16) char sm[];
    const uint32_t sb = smem_u32(sm);
    const int tid = threadIdx.x, w = tid >> 5, lane = tid & 31;
    const int m0 = (w & 3) * 32, n0w = (w >> 2) * 128;
    const int rowBase = blockIdx.x * 128;

    float* bias1s = (float*)(sm + OFF_B1S);
    float* bias2s = (float*)(sm + OFF_B2S);
    float* axinv  = (float*)(sm + OFF_AUX);
    float* pfs    = (float*)(sm + OFF_FRS);   // pooled frac mean per row
    float* wfr    = (float*)(sm + OFF_WFR);   // iW1 row 128

    bias1s[tid] = b1v[tid];
    bias2s[tid] = b2v[tid];
    wfr[tid]    = iW1[128 * 256 + tid];
    if (tid < 128) {
        int gr = rowBase + tid;
        float c = (gr < M_SEG) ? g_counts[gr] : 1.f;
        float inv = 1.f / fmaxf(c, 1.f);
        axinv[tid] = inv;
        pfs[tid] = (gr < M_SEG)
            ? __half2float(g_pooled[(size_t)gr * PHSTR + 128]) * inv : 0.f;
    }
    __syncthreads();

    // gather A1: pooled cols 0..127 (2 threads per row, 64 cols each)
    {
        const int gr_ = tid >> 1, ghalf = tid & 1;
        const int rg = rowBase + gr_;
        const int kk0 = ghalf * 64;
        float inv = axinv[gr_];
        uint32_t base = sb + OFF_A10 + (uint32_t)gr_ * ASTR1 + (uint32_t)kk0 * 2;
#pragma unroll
        for (int i = 0; i < 16; i++) {
            int kk = kk0 + i * 4;
            float4 v = make_float4(0.f, 0.f, 0.f, 0.f);
            if (rg < M_SEG) {
                const __half2* hp = (const __half2*)&g_pooled[(size_t)rg * PHSTR + kk];
                float2 f01 = __half22float2(hp[0]), f23 = __half22float2(hp[1]);
                v = make_float4(f01.x * inv, f01.y * inv, f23.x * inv, f23.y * inv);
            }
            STSV2(base + i * 8, pack2h(v.x, v.y), pack2h(v.z, v.w));
        }
    }
    cp_chunk(sb + OFF_BB0, g_mw1, 0, tid); CP_COMMIT();

    float acc[2][16][4];
    CLR_ACC();
    const int rb = m0 + (lane >> 2);
    const int cb = n0w + (lane & 3) * 2;

    // -------- L1: 1 chunk --------
    CP_WAIT0(); __syncthreads();
    cp_chunk(sb + OFF_BB1, g_mw2, 0, tid); CP_COMMIT();
    mma_chunk(acc, sb + OFF_A10, ASTR1, sb + OFF_BB0, lane, m0, n0w);
    __syncthreads();   // MMA reads of A1 done before epi1 writes A2 (aliased)

    // epi1: + pf*wfr + b1 -> softplus -> A2 (fp16)
    {
        float pf[4];
#pragma unroll
        for (int q = 0; q < 4; q++)
            pf[q] = pfs[rb + (q >> 1) * 16 + (q & 1) * 8];
#pragma unroll
        for (int mi = 0; mi < 2; mi++)
#pragma unroll
            for (int ni = 0; ni < 16; ni++) {
                int col = cb + ni * 8;
                float2 bb = *(float2*)&bias1s[col];
                float2 wf = *(float2*)&wfr[col];
                int row = rb + mi * 16;
                uint32_t ad = sb + OFF_A2 + (uint32_t)row * ASTR2 + (uint32_t)col * 2;
                STS32(ad, pack2h(sp(acc[mi][ni][0] + pf[mi*2]*wf.x + bb.x),
                                 sp(acc[mi][ni][1] + pf[mi*2]*wf.y + bb.y)));
                STS32(ad + 8*ASTR2, pack2h(sp(acc[mi][ni][2] + pf[mi*2+1]*wf.x + bb.x),
                                           sp(acc[mi][ni][3] + pf[mi*2+1]*wf.y + bb.y)));
            }
    }
    CLR_ACC();

    // -------- L2: 2 chunks --------
    CP_WAIT0(); __syncthreads();                       // BB1 ready, epi1 visible
    cp_chunk(sb + OFF_BB0, g_mw2, 1, tid); CP_COMMIT();
    mma_chunk(acc, sb + OFF_A2, ASTR2, sb + OFF_BB1, lane, m0, n0w);
    CP_WAIT0(); __syncthreads();
    cp_chunk(sb + OFF_BB1, g_gwc, 0, tid); CP_COMMIT();
    mma_chunk(acc, sb + OFF_A2 + 256, ASTR2, sb + OFF_BB0, lane, m0, n0w);
    __syncthreads();   // MMA reads of A2 done before epi2 rewrites A2

    // epi2 -> ctx fp16 in A2
#pragma unroll
    for (int mi = 0; mi < 2; mi++)
#pragma unroll
        for (int ni = 0; ni < 16; ni++) {
            int col = cb + ni * 8;
            float2 bb = *(float2*)&bias2s[col];
            int row = rb + mi * 16;
            uint32_t ad = sb + OFF_A2 + (uint32_t)row * ASTR2 + (uint32_t)col * 2;
            STS32(ad, pack2h(sp(acc[mi][ni][0]+bb.x), sp(acc[mi][ni][1]+bb.y)));
            STS32(ad + 8*ASTR2, pack2h(sp(acc[mi][ni][2]+bb.x), sp(acc[mi][ni][3]+bb.y)));
        }
    CLR_ACC();

    // -------- L3: 2 chunks --------
    CP_WAIT0(); __syncthreads();
    cp_chunk(sb + OFF_BB0, g_gwc, 1, tid); CP_COMMIT();
    mma_chunk(acc, sb + OFF_A2, ASTR2, sb + OFF_BB1, lane, m0, n0w);
    CP_WAIT0(); __syncthreads();
    mma_chunk(acc, sb + OFF_A2 + 256, ASTR2, sb + OFF_BB0, lane, m0, n0w);

    // epi3 -> g_ctxpre (fp32)
#pragma unroll
    for (int mi = 0; mi < 2; mi++)
#pragma unroll
        for (int ni = 0; ni < 16; ni++) {
            int col = cb + ni * 8;
            int gr = rowBase + rb + mi * 16;
            if (gr < M_SEG)
                *(float2*)&g_ctxpre[(size_t)gr * 256 + col] =
                    make_float2(acc[mi][ni][0], acc[mi][ni][1]);
            if (gr + 8 < M_SEG)
                *(float2*)&g_ctxpre[(size_t)(gr+8) * 256 + col] =
                    make_float2(acc[mi][ni][2], acc[mi][ni][3]);
        }
}

// ---------------------------------------------------------------------------
// gate: emb L1 (1 chunk) + ctxpre[seg] + frac*w128 epi -> softplus -> L2 (2) -> out
__global__ __launch_bounds__(256, 1)
void k_gate(const float* __restrict__ emb, const float* __restrict__ frac,
            const int* __restrict__ seg, const float* __restrict__ gW1,
            const float* __restrict__ b1v, const float* __restrict__ b2v,
            float* __restrict__ outp) {
    extern __shared__ __align__(16) char sm[];
    const uint32_t sb = smem_u32(sm);
    const int tid = threadIdx.x, w = tid >> 5, lane = tid & 31;
    const int m0 = (w & 3) * 32, n0w = (w >> 2) * 128;
    const int rowBase = blockIdx.x * 128;

    float* bias1s = (float*)(sm + OFF_B1S);
    float* bias2s = (float*)(sm + OFF_B2S);
    int*   axseg  = (int*)  (sm + OFF_AUX);
    float* fracs  = (float*)(sm + OFF_FRS);
    float* wfrac  = (float*)(sm + OFF_WFR);

    bias1s[tid] = b1v[tid];
    bias2s[tid] = b2v[tid];
    wfrac[tid]  = gW1[128 * 256 + tid];
    if (tid < 128) {
        axseg[tid] = seg[rowBase + tid];
        fracs[tid] = frac[rowBase + tid];
    }

    // gather A1: emb cols 0..127 (no dependency on the smem preamble)
    {
        const int gr_ = tid >> 1, ghalf = tid & 1;
        const long long rg = rowBase + gr_;
        const int kk0 = ghalf * 64;
        uint32_t base = sb + OFF_A10 + (uint32_t)gr_ * ASTR1 + (uint32_t)kk0 * 2;
#pragma unroll
        for (int i = 0; i < 16; i++) {
            float4 v = *(const float4*)&emb[rg * EMB + kk0 + i * 4];
            STSV2(base + i * 8, pack2h(v.x, v.y), pack2h(v.z, v.w));
        }
    }
    cp_chunk(sb + OFF_BB0, g_gwe, 0, tid); CP_COMMIT();

    float acc[2][16][4];
    CLR_ACC();
    const int rb = m0 + (lane >> 2);
    const int cb = n0w + (lane & 3) * 2;

    // -------- L1: 1 chunk --------
    CP_WAIT0(); __syncthreads();
    cp_chunk(sb + OFF_BB1, g_gw2, 0, tid); CP_COMMIT();
    mma_chunk(acc, sb + OFF_A10, ASTR1, sb + OFF_BB0, lane, m0, n0w);
    __syncthreads();   // A1 reads done before epi1 writes A2 (aliased)

    // epi1: acc += ctxpre[seg] + frac*wfrac + b1 -> softplus -> A2
    {
        int sgl[4]; float fr[4];
#pragma unroll
        for (int q = 0; q < 4; q++) {
            int row = rb + (q >> 1) * 16 + (q & 1) * 8;
            sgl[q] = axseg[row];
            fr[q]  = fracs[row];
        }
#pragma unroll
        for (int mi = 0; mi < 2; mi++)
#pragma unroll
            for (int ni = 0; ni < 16; ni++) {
                int col = cb + ni * 8;
                float2 bb = *(float2*)&bias1s[col];
                float2 wf = *(float2*)&wfrac[col];
                float2 c0 = *(const float2*)&g_ctxpre[(size_t)sgl[mi*2]   * 256 + col];
                float2 c1 = *(const float2*)&g_ctxpre[(size_t)sgl[mi*2+1] * 256 + col];
                int row = rb + mi * 16;
                uint32_t ad = sb + OFF_A2 + (uint32_t)row * ASTR2 + (uint32_t)col * 2;
                STS32(ad, pack2h(sp(acc[mi][ni][0] + c0.x + fr[mi*2]*wf.x + bb.x),
                                 sp(acc[mi][ni][1] + c0.y + fr[mi*2]*wf.y + bb.y)));
                STS32(ad + 8*ASTR2, pack2h(sp(acc[mi][ni][2] + c1.x + fr[mi*2+1]*wf.x + bb.x),
                                           sp(acc[mi][ni][3] + c1.y + fr[mi*2+1]*wf.y + bb.y)));
            }
    }
    CLR_ACC();

    // -------- L2: 2 chunks --------
    CP_WAIT0(); __syncthreads();                       // BB1 ready, epi1 visible
    cp_chunk(sb + OFF_BB0, g_gw2, 1, tid); CP_COMMIT();
    mma_chunk(acc, sb + OFF_A2, ASTR2, sb + OFF_BB1, lane, m0, n0w);
    CP_WAIT0(); __syncthreads();
    mma_chunk(acc, sb + OFF_A2 + 256, ASTR2, sb + OFF_BB0, lane, m0, n0w);

    // epi2 -> out
#pragma unroll
    for (int mi = 0; mi < 2; mi++)
#pragma unroll
        for (int ni = 0; ni < 16; ni++) {
            int col = cb + ni * 8;
            float2 bb = *(float2*)&bias2s[col];
            int gr = rowBase + rb + mi * 16;
            *(float2*)&outp[(long long)gr * 256 + col] =
                make_float2(sp(acc[mi][ni][0]+bb.x), sp(acc[mi][ni][1]+bb.y));
            *(float2*)&outp[(long long)(gr+8) * 256 + col] =
                make_float2(sp(acc[mi][ni][2]+bb.x), sp(acc[mi][ni][3]+bb.y));
        }
}

// ---------------------------------------------------------------------------
extern "C" void kernel_launch(void* const* d_in, const int* in_sizes, int n_in,
                              void* d_out, int out_size) {
    const float* emb  = (const float*)d_in[0];
    const float* frac = (const float*)d_in[1];
    const int*   seg  = (const int*)  d_in[2];
    const float* iW1  = (const float*)d_in[3];
    const float* ib1  = (const float*)d_in[4];
    const float* iW2  = (const float*)d_in[5];
    const float* ib2  = (const float*)d_in[6];
    const float* gW1  = (const float*)d_in[7];
    const float* gb1  = (const float*)d_in[8];
    const float* gW2  = (const float*)d_in[9];
    const float* gb2  = (const float*)d_in[10];
    float* out = (float*)d_out;

    cudaFuncSetAttribute(k_mix,  cudaFuncAttributeMaxDynamicSharedMemorySize, SMEM_TOTAL);
    cudaFuncSetAttribute(k_gate, cudaFuncAttributeMaxDynamicSharedMemorySize, SMEM_TOTAL);

    k_prep<<<(1*CHW + 255)/256, 256>>>(gW1, 0, 1, 128, 0);   // g_gwe
    k_prep<<<(2*CHW + 255)/256, 256>>>(gW1, 2, 2, 256, 1);   // g_gwc
    k_prep<<<(2*CHW + 255)/256, 256>>>(gW2, 0, 2, 256, 2);   // g_gw2
    k_prep<<<(1*CHW + 255)/256, 256>>>(iW1, 0, 1, 128, 3);   // g_mw1
    k_prep<<<(2*CHW + 255)/256, 256>>>(iW2, 0, 2, 256, 4);   // g_mw2

    long long totz = (long long)M_SEG * PHSTR / 2 + M_SEG;
    k_zero<<<(unsigned)((totz + 255)/256), 256>>>();

    float* out_frac = nullptr;
    if ((long long)out_size >= (long long)N_ROWS * (LAT + 1))
        out_frac = out + (size_t)N_ROWS * LAT;
    long long tota = (long long)N_ROWS * 17;
    k_accum<<<(unsigned)((tota + 255)/256), 256>>>(emb, frac, seg, out_frac);

    k_mix<<<(M_SEG + 127)/128, 256, SMEM_TOTAL>>>(iW1, ib1, ib2);
    k_gate<<<N_ROWS / 128, 256, SMEM_TOTAL>>>(emb, frac, seg, gW1, gb1, gb2, out);
}

// round 15
// speedup vs baseline: 1.7354x; 1.3382x over previous
#include <cuda_runtime.h>
#include <cuda_fp16.h>
#include <cstdint>
#include <math.h>

#define N_ROWS 400000
#define M_SEG  100000
#define EMB    128
#define CTX    256
#define LAT    256
#define PHSTR  136           // pooled row stride in halves

#define CHW 18432            // halves per 64-wide B chunk image (256 x 72 = 36864 B)
#define ASTR1 144            // A1 row stride bytes
#define ASTR2 528            // A2 row stride bytes

// smem layout (bytes) — total 109KB -> 2 CTAs/SM
#define OFF_B1S   0          // bias1: 256 f32
#define OFF_B2S   1024       // bias2: 256 f32
#define OFF_AUX   2048       // axseg/axinv: 64 x 4B
#define OFF_FRS   2560       // per-row scalar: 64 f32
#define OFF_WFR   3072       // rank-1 weight row: 256 f32 -> 4096
#define OFF_A2    4096       // A2: 64 x 528B = 33792 -> 37888
#define OFF_A10   4096       // A1 buf0 (aliases A2 lower): 64 x 144 = 9216
#define OFF_A11   13312      // A1 buf1 (aliases A2 upper): 9216 -> 22528
#define OFF_BB0   37888      // B buf0: 36864 -> 74752
#define OFF_BB1   74752      // B buf1: 36864 -> 111616
#define SMEM_TOTAL 111616

// scratch globals
__device__ __align__(16) __half g_pooled[(size_t)M_SEG * PHSTR];
__device__ float g_counts[M_SEG];
__device__ float g_ctxpre[(size_t)M_SEG * CTX];   // ctx @ gW1[129:385], fp32
// prepped B chunk images: [chunk][256][72] fp16 RN
__device__ __align__(16) __half g_gwe[2*CHW];   // gate W1 rows 0..127
__device__ __align__(16) __half g_gwc[4*CHW];   // gate W1 rows 129..384
__device__ __align__(16) __half g_gw2[4*CHW];
__device__ __align__(16) __half g_mw1[2*CHW];   // iW1 rows 0..127 (row 128 -> rank-1 epi)
__device__ __align__(16) __half g_mw2[4*CHW];

__device__ __forceinline__ uint32_t smem_u32(const void* p) {
    uint32_t a;
    asm("{ .reg .u64 t; cvta.to.shared.u64 t, %1; cvt.u32.u64 %0, t; }" : "=r"(a) : "l"(p));
    return a;
}
#define LDSM4(r0,r1,r2,r3,addr) \
    asm volatile("ldmatrix.sync.aligned.m8n8.x4.shared.b16 {%0,%1,%2,%3}, [%4];" \
        : "=r"(r0),"=r"(r1),"=r"(r2),"=r"(r3) : "r"(addr))
#define MMA(d,a,b0,b1) \
    asm volatile("mma.sync.aligned.m16n8k16.row.col.f32.f16.f16.f32 " \
        "{%0,%1,%2,%3},{%4,%5,%6,%7},{%8,%9},{%0,%1,%2,%3};" \
        : "+f"((d)[0]),"+f"((d)[1]),"+f"((d)[2]),"+f"((d)[3]) \
        : "r"((a)[0]),"r"((a)[1]),"r"((a)[2]),"r"((a)[3]),"r"(b0),"r"(b1))
#define CP16(sa,gp) asm volatile("cp.async.cg.shared.global [%0], [%1], 16;" :: "r"(sa),"l"(gp))
#define CP_COMMIT() asm volatile("cp.async.commit_group;" ::: "memory")
#define CP_WAIT0()  asm volatile("cp.async.wait_group 0;" ::: "memory")
#define STS32(a,v)  asm volatile("st.shared.b32 [%0], %1;" :: "r"(a),"r"(v) : "memory")
#define STSV2(a,x,y) asm volatile("st.shared.v2.b32 [%0], {%1,%2};" :: "r"(a),"r"(x),"r"(y) : "memory")
#define REDH2V4(p,a,b,c,d) \
    asm volatile("red.global.add.noftz.v4.f16x2 [%0], {%1,%2,%3,%4};" \
        :: "l"(p), "r"(a), "r"(b), "r"(c), "r"(d) : "memory")
#define REDH2(p,a) \
    asm volatile("red.global.add.noftz.f16x2 [%0], %1;" :: "l"(p), "r"(a) : "memory")

__device__ __forceinline__ float sp(float x) {
    return fmaxf(x, 0.f) + __logf(1.f + __expf(-fabsf(x)));
}
__device__ __forceinline__ uint32_t pack2h(float a, float b) {
    __half2 h = __floats2half2_rn(a, b);
    return *(uint32_t*)&h;
}

// ---------------------------------------------------------------------------
__global__ void k_zero() {
    long long i = (long long)blockIdx.x * 256 + threadIdx.x;
    const long long P = (long long)M_SEG * PHSTR / 2;
    if (i < P) ((uint32_t*)g_pooled)[i] = 0u;
    else if (i < P + M_SEG) g_counts[i - P] = 0.f;
}

__global__ void k_accum(const float* __restrict__ emb, const float* __restrict__ frac,
                        const int* __restrict__ seg, float* __restrict__ out_frac) {
    int idx = blockIdx.x * 256 + threadIdx.x;
    if (idx >= N_ROWS * 17) return;
    int r = idx / 17;
    int g = idx - r * 17;
    int s = seg[r];
    if (g < 16) {
        const float4* e = (const float4*)&emb[(long long)r * EMB + g * 8];
        float4 a = e[0], b = e[1];
        REDH2V4(&g_pooled[(size_t)s * PHSTR + g * 8],
                pack2h(a.x, a.y), pack2h(a.z, a.w),
                pack2h(b.x, b.y), pack2h(b.z, b.w));
    } else {
        float f = frac[r];
        REDH2(&g_pooled[(size_t)s * PHSTR + 128], pack2h(f, 0.f));
        atomicAdd(&g_counts[s], 1.f);
        if (out_frac) out_frac[r] = f;
    }
}

// prep: W -> chunk images [c][n][72] fp16 RN (64 data + 8 pad)
// mode 0: rows c*64+kk (< Kreal); mode 2: rows c*64+kk+129 (< 256 data rows)
__global__ void k_prep(const float* __restrict__ W, int mode, int nch, int Kreal, int which) {
    __half* dh;
    if (which == 0)      dh = g_gwe;
    else if (which == 1) dh = g_gwc;
    else if (which == 2) dh = g_gw2;
    else if (which == 3) dh = g_mw1;
    else                 dh = g_mw2;
    int idx = blockIdx.x * 256 + threadIdx.x;
    if (idx >= nch * CHW) return;
    int c = idx / CHW, rem = idx - c * CHW;
    int n = rem / 72, kk = rem - n * 72;
    float v = 0.f;
    if (kk < 64) {
        int kg = c * 64 + kk, sr;
        if (mode == 2) sr = (kg < 256) ? kg + 129 : -1;
        else           sr = (kg < Kreal) ? kg : -1;
        if (sr >= 0) v = W[(long long)sr * 256 + n];
    }
    dh[idx] = __float2half_rn(v);
}

// ---------------------------------------------------------------------------
__device__ __forceinline__ void cp_chunk(uint32_t dst, const __half* src, int c, int tid) {
    const uint4* gp = (const uint4*)src + (long long)c * (CHW / 8);
#pragma unroll
    for (int j = 0; j < 9; j++) {
        int i = tid + j * 256;
        CP16(dst + i * 16, gp + i);
    }
}

// fp16 MMA over one 64-wide K chunk; warp tile 32x64; B stride 144B
__device__ __forceinline__ void mma_chunk(float (&acc)[2][8][4],
                                          uint32_t aBase, int aStride,
                                          uint32_t bBase,
                                          int lane, int m0, int n0w) {
    const int arow = (lane & 7) + ((lane >> 3) & 1) * 8;
    const int brow = (lane & 7) + (lane >> 4) * 8;
    const int bk0  = ((lane >> 3) & 1) * 16;
#pragma unroll
    for (int ks = 0; ks < 4; ks++) {
        uint32_t ah[2][4];
        int akb = ks * 32 + (lane >> 4) * 16;
#pragma unroll
        for (int mi = 0; mi < 2; mi++) {
            uint32_t ra = aBase + (uint32_t)(m0 + mi * 16 + arow) * aStride + akb;
            LDSM4(ah[mi][0], ah[mi][1], ah[mi][2], ah[mi][3], ra);
        }
        int bkb = ks * 32 + bk0;
#pragma unroll
        for (int g = 0; g < 4; g++) {
            uint32_t bh[4];
            uint32_t ro = (uint32_t)(n0w + g * 16 + brow) * 144 + bkb;
            LDSM4(bh[0], bh[1], bh[2], bh[3], bBase + ro);
#pragma unroll
            for (int mi = 0; mi < 2; mi++) {
                MMA(acc[mi][2*g],   ah[mi], bh[0], bh[1]);
                MMA(acc[mi][2*g+1], ah[mi], bh[2], bh[3]);
            }
        }
    }
}

#define CLR_ACC() \
    _Pragma("unroll") for (int i_ = 0; i_ < 2; i_++) \
    _Pragma("unroll") for (int j_ = 0; j_ < 8; j_++) \
    _Pragma("unroll") for (int q_ = 0; q_ < 4; q_++) acc[i_][j_][q_] = 0.f

// ---------------------------------------------------------------------------
// mix: pooled mean L1 (2 chunks) + frac rank-1 epi -> L2 (4) -> ctx -> L3 (4)
//      -> g_ctxpre (fp32).  Tile 64x256, 2 CTAs/SM.
__global__ __launch_bounds__(256, 2)
void k_mix(const float* __restrict__ iW1,
           const float* __restrict__ b1v, const float* __restrict__ b2v) {
    extern __shared__ __align__(16) char sm[];
    const uint32_t sb = smem_u32(sm);
    const int tid = threadIdx.x, w = tid >> 5, lane = tid & 31;
    const int m0 = (w & 1) * 32, n0w = (w >> 1) * 64;
    const int rowBase = blockIdx.x * 64;

    float* bias1s = (float*)(sm + OFF_B1S);
    float* bias2s = (float*)(sm + OFF_B2S);
    float* axinv  = (float*)(sm + OFF_AUX);
    float* pfs    = (float*)(sm + OFF_FRS);
    float* wfr    = (float*)(sm + OFF_WFR);

    bias1s[tid] = b1v[tid];
    bias2s[tid] = b2v[tid];
    wfr[tid]    = iW1[128 * 256 + tid];
    if (tid < 64) {
        int gr = rowBase + tid;
        float c = (gr < M_SEG) ? g_counts[gr] : 1.f;
        float inv = 1.f / fmaxf(c, 1.f);
        axinv[tid] = inv;
        pfs[tid] = (gr < M_SEG)
            ? __half2float(g_pooled[(size_t)gr * PHSTR + 128]) * inv : 0.f;
    }
    __syncthreads();

    const int gr_ = tid >> 2, gq = tid & 3;   // 4 threads per row, 16 cols each
    const int rg = rowBase + gr_;
    const int kk0 = gq * 16;
    auto gather = [&](int c, uint32_t (&ar)[8]) {
        float inv = axinv[gr_];
#pragma unroll
        for (int i = 0; i < 4; i++) {
            int k = c * 64 + kk0 + i * 4;
            float4 v = make_float4(0.f, 0.f, 0.f, 0.f);
            if (rg < M_SEG) {
                const __half2* hp = (const __half2*)&g_pooled[(size_t)rg * PHSTR + k];
                float2 f01 = __half22float2(hp[0]), f23 = __half22float2(hp[1]);
                v = make_float4(f01.x * inv, f01.y * inv, f23.x * inv, f23.y * inv);
            }
            ar[2*i]   = pack2h(v.x, v.y);
            ar[2*i+1] = pack2h(v.z, v.w);
        }
    };
    auto stsA = [&](uint32_t abuf, const uint32_t (&ar)[8]) {
        uint32_t base = abuf + (uint32_t)gr_ * ASTR1 + (uint32_t)kk0 * 2;
#pragma unroll
        for (int i = 0; i < 4; i++)
            STSV2(base + i * 8, ar[2*i], ar[2*i+1]);
    };

    float acc[2][8][4];
    CLR_ACC();
    const int rb = m0 + (lane >> 2);
    const int cb = n0w + (lane & 3) * 2;

    // -------- L1: 2 chunks --------
    {
        uint32_t ar[8];
        gather(0, ar); stsA(sb + OFF_A10, ar);
        cp_chunk(sb + OFF_BB0, g_mw1, 0, tid); CP_COMMIT();
    }
    for (int c = 0; c < 2; ++c) {
        uint32_t ar[8];
        if (c + 1 < 2) gather(c + 1, ar);
        CP_WAIT0();
        __syncthreads();
        if (c + 1 < 2) { cp_chunk(sb + OFF_BB1, g_mw1, 1, tid); CP_COMMIT(); }
        mma_chunk(acc, sb + ((c & 1) ? OFF_A11 : OFF_A10), ASTR1,
                  sb + ((c & 1) ? OFF_BB1 : OFF_BB0), lane, m0, n0w);
        if (c + 1 < 2) stsA(sb + OFF_A11, ar);
    }
    __syncthreads();   // all A1 reads done before epi1 writes A2 (aliased)
    cp_chunk(sb + OFF_BB0, g_mw2, 0, tid); CP_COMMIT();   // L2 chunk0 -> BB0

    // epi1: + pf*wfr + b1 -> softplus -> A2 (fp16)
    {
        float pf[4];
#pragma unroll
        for (int q = 0; q < 4; q++)
            pf[q] = pfs[rb + (q >> 1) * 16 + (q & 1) * 8];
#pragma unroll
        for (int mi = 0; mi < 2; mi++)
#pragma unroll
            for (int ni = 0; ni < 8; ni++) {
                int col = cb + ni * 8;
                float2 bb = *(float2*)&bias1s[col];
                float2 wf = *(float2*)&wfr[col];
                int row = rb + mi * 16;
                uint32_t ad = sb + OFF_A2 + (uint32_t)row * ASTR2 + (uint32_t)col * 2;
                STS32(ad, pack2h(sp(acc[mi][ni][0] + pf[mi*2]*wf.x + bb.x),
                                 sp(acc[mi][ni][1] + pf[mi*2]*wf.y + bb.y)));
                STS32(ad + 8*ASTR2, pack2h(sp(acc[mi][ni][2] + pf[mi*2+1]*wf.x + bb.x),
                                           sp(acc[mi][ni][3] + pf[mi*2+1]*wf.y + bb.y)));
            }
    }
    CLR_ACC();

    // -------- L2: 4 chunks (cur = c&1 ? BB1 : BB0) --------
    for (int c = 0; c < 4; ++c) {
        CP_WAIT0();
        __syncthreads();
        if (c + 1 < 4) { cp_chunk(sb + (((c+1)&1)?OFF_BB1:OFF_BB0), g_mw2, c+1, tid); CP_COMMIT(); }
        else           { cp_chunk(sb + OFF_BB0, g_gwc, 0, tid); CP_COMMIT(); }  // c=3 cur=BB1, BB0 free
        mma_chunk(acc, sb + OFF_A2 + (uint32_t)c * 128, ASTR2,
                  sb + ((c&1)?OFF_BB1:OFF_BB0), lane, m0, n0w);
    }
    __syncthreads();   // all A2 reads done before epi2 rewrites A2

    // epi2 -> ctx fp16 in A2
#pragma unroll
    for (int mi = 0; mi < 2; mi++)
#pragma unroll
        for (int ni = 0; ni < 8; ni++) {
            int col = cb + ni * 8;
            float2 bb = *(float2*)&bias2s[col];
            int row = rb + mi * 16;
            uint32_t ad = sb + OFF_A2 + (uint32_t)row * ASTR2 + (uint32_t)col * 2;
            STS32(ad, pack2h(sp(acc[mi][ni][0]+bb.x), sp(acc[mi][ni][1]+bb.y)));
            STS32(ad + 8*ASTR2, pack2h(sp(acc[mi][ni][2]+bb.x), sp(acc[mi][ni][3]+bb.y)));
        }
    CLR_ACC();

    // -------- L3: 4 chunks (cur = c&1 ? BB1 : BB0; chunk0 in BB0) --------
    for (int c = 0; c < 4; ++c) {
        CP_WAIT0();
        __syncthreads();
        if (c + 1 < 4) { cp_chunk(sb + (((c+1)&1)?OFF_BB1:OFF_BB0), g_gwc, c+1, tid); CP_COMMIT(); }
        mma_chunk(acc, sb + OFF_A2 + (uint32_t)c * 128, ASTR2,
                  sb + ((c&1)?OFF_BB1:OFF_BB0), lane, m0, n0w);
    }

    // epi3 -> g_ctxpre (fp32)
#pragma unroll
    for (int mi = 0; mi < 2; mi++)
#pragma unroll
        for (int ni = 0; ni < 8; ni++) {
            int col = cb + ni * 8;
            int gr = rowBase + rb + mi * 16;
            if (gr < M_SEG)
                *(float2*)&g_ctxpre[(size_t)gr * 256 + col] =
                    make_float2(acc[mi][ni][0], acc[mi][ni][1]);
            if (gr + 8 < M_SEG)
                *(float2*)&g_ctxpre[(size_t)(gr+8) * 256 + col] =
                    make_float2(acc[mi][ni][2], acc[mi][ni][3]);
        }
}

// ---------------------------------------------------------------------------
// gate: emb L1 (2 chunks) + ctxpre[seg] + frac*w128 epi -> L2 (4) -> out
//       Tile 64x256, 2 CTAs/SM.
__global__ __launch_bounds__(256, 2)
void k_gate(const float* __restrict__ emb, const float* __restrict__ frac,
            const int* __restrict__ seg, const float* __restrict__ gW1,
            const float* __restrict__ b1v, const float* __restrict__ b2v,
            float* __restrict__ outp) {
    extern __shared__ __align__(16) char sm[];
    const uint32_t sb = smem_u32(sm);
    const int tid = threadIdx.x, w = tid >> 5, lane = tid & 31;
    const int m0 = (w & 1) * 32, n0w = (w >> 1) * 64;
    const int rowBase = blockIdx.x * 64;

    float* bias1s = (float*)(sm + OFF_B1S);
    float* bias2s = (float*)(sm + OFF_B2S);
    int*   axseg  = (int*)  (sm + OFF_AUX);
    float* fracs  = (float*)(sm + OFF_FRS);
    float* wfrac  = (float*)(sm + OFF_WFR);

    bias1s[tid] = b1v[tid];
    bias2s[tid] = b2v[tid];
    wfrac[tid]  = gW1[128 * 256 + tid];
    if (tid < 64) {
        axseg[tid] = seg[rowBase + tid];
        fracs[tid] = frac[rowBase + tid];
    }

    const int gr_ = tid >> 2, gq = tid & 3;
    const long long rg = rowBase + gr_;
    const int kk0 = gq * 16;
    auto gatherE = [&](int c, uint32_t (&ar)[8]) {
#pragma unroll
        for (int i = 0; i < 4; i++) {
            float4 v = *(const float4*)&emb[rg * EMB + c * 64 + kk0 + i * 4];
            ar[2*i]   = pack2h(v.x, v.y);
            ar[2*i+1] = pack2h(v.z, v.w);
        }
    };
    auto stsA = [&](uint32_t abuf, const uint32_t (&ar)[8]) {
        uint32_t base = abuf + (uint32_t)gr_ * ASTR1 + (uint32_t)kk0 * 2;
#pragma unroll
        for (int i = 0; i < 4; i++)
            STSV2(base + i * 8, ar[2*i], ar[2*i+1]);
    };

    float acc[2][8][4];
    CLR_ACC();
    const int rb = m0 + (lane >> 2);
    const int cb = n0w + (lane & 3) * 2;

    // -------- L1: 2 chunks --------
    {
        uint32_t ar[8];
        gatherE(0, ar); stsA(sb + OFF_A10, ar);
        cp_chunk(sb + OFF_BB0, g_gwe, 0, tid); CP_COMMIT();
    }
    for (int c = 0; c < 2; ++c) {
        uint32_t ar[8];
        if (c + 1 < 2) gatherE(c + 1, ar);
        CP_WAIT0();
        __syncthreads();    // also makes axseg/fracs/bias visible (first iter)
        if (c + 1 < 2) { cp_chunk(sb + OFF_BB1, g_gwe, 1, tid); CP_COMMIT(); }
        mma_chunk(acc, sb + ((c & 1) ? OFF_A11 : OFF_A10), ASTR1,
                  sb + ((c & 1) ? OFF_BB1 : OFF_BB0), lane, m0, n0w);
        if (c + 1 < 2) stsA(sb + OFF_A11, ar);
    }
    __syncthreads();   // A1 reads done before epi1 writes A2 (aliased)
    cp_chunk(sb + OFF_BB0, g_gw2, 0, tid); CP_COMMIT();   // L2 chunk0 -> BB0

    // epi1: acc += ctxpre[seg] + frac*wfrac + b1 -> softplus -> A2
    {
        int sgl[4]; float fr[4];
#pragma unroll
        for (int q = 0; q < 4; q++) {
            int row = rb + (q >> 1) * 16 + (q & 1) * 8;
            sgl[q] = axseg[row];
            fr[q]  = fracs[row];
        }
#pragma unroll
        for (int mi = 0; mi < 2; mi++)
#pragma unroll
            for (int ni = 0; ni < 8; ni++) {
                int col = cb + ni * 8;
                float2 bb = *(float2*)&bias1s[col];
                float2 wf = *(float2*)&wfrac[col];
                float2 c0 = *(const float2*)&g_ctxpre[(size_t)sgl[mi*2]   * 256 + col];
                float2 c1 = *(const float2*)&g_ctxpre[(size_t)sgl[mi*2+1] * 256 + col];
                int row = rb + mi * 16;
                uint32_t ad = sb + OFF_A2 + (uint32_t)row * ASTR2 + (uint32_t)col * 2;
                STS32(ad, pack2h(sp(acc[mi][ni][0] + c0.x + fr[mi*2]*wf.x + bb.x),
                                 sp(acc[mi][ni][1] + c0.y + fr[mi*2]*wf.y + bb.y)));
                STS32(ad + 8*ASTR2, pack2h(sp(acc[mi][ni][2] + c1.x + fr[mi*2+1]*wf.x + bb.x),
                                           sp(acc[mi][ni][3] + c1.y + fr[mi*2+1]*wf.y + bb.y)));
            }
    }
    CLR_ACC();

    // -------- L2: 4 chunks (cur = c&1 ? BB1 : BB0) --------
    for (int c = 0; c < 4; ++c) {
        CP_WAIT0();
        __syncthreads();   // iter0: epi1 STS visible
        if (c + 1 < 4) { cp_chunk(sb + (((c+1)&1)?OFF_BB1:OFF_BB0), g_gw2, c+1, tid); CP_COMMIT(); }
        mma_chunk(acc, sb + OFF_A2 + (uint32_t)c * 128, ASTR2,
                  sb + ((c&1)?OFF_BB1:OFF_BB0), lane, m0, n0w);
    }

    // epi2 -> out
#pragma unroll
    for (int mi = 0; mi < 2; mi++)
#pragma unroll
        for (int ni = 0; ni < 8; ni++) {
            int col = cb + ni * 8;
            float2 bb = *(float2*)&bias2s[col];
            int gr = rowBase + rb + mi * 16;
            *(float2*)&outp[(long long)gr * 256 + col] =
                make_float2(sp(acc[mi][ni][0]+bb.x), sp(acc[mi][ni][1]+bb.y));
            *(float2*)&outp[(long long)(gr+8) * 256 + col] =
                make_float2(sp(acc[mi][ni][2]+bb.x), sp(acc[mi][ni][3]+bb.y));
        }
}

// ---------------------------------------------------------------------------
extern "C" void kernel_launch(void* const* d_in, const int* in_sizes, int n_in,
                              void* d_out, int out_size) {
    const float* emb  = (const float*)d_in[0];
    const float* frac = (const float*)d_in[1];
    const int*   seg  = (const int*)  d_in[2];
    const float* iW1  = (const float*)d_in[3];
    const float* ib1  = (const float*)d_in[4];
    const float* iW2  = (const float*)d_in[5];
    const float* ib2  = (const float*)d_in[6];
    const float* gW1  = (const float*)d_in[7];
    const float* gb1  = (const float*)d_in[8];
    const float* gW2  = (const float*)d_in[9];
    const float* gb2  = (const float*)d_in[10];
    float* out = (float*)d_out;

    cudaFuncSetAttribute(k_mix,  cudaFuncAttributeMaxDynamicSharedMemorySize, SMEM_TOTAL);
    cudaFuncSetAttribute(k_gate, cudaFuncAttributeMaxDynamicSharedMemorySize, SMEM_TOTAL);

    k_prep<<<(2*CHW + 255)/256, 256>>>(gW1, 0, 2, 128, 0);   // g_gwe
    k_prep<<<(4*CHW + 255)/256, 256>>>(gW1, 2, 4, 256, 1);   // g_gwc
    k_prep<<<(4*CHW + 255)/256, 256>>>(gW2, 0, 4, 256, 2);   // g_gw2
    k_prep<<<(2*CHW + 255)/256, 256>>>(iW1, 0, 2, 128, 3);   // g_mw1 (row 128 -> epi)
    k_prep<<<(4*CHW + 255)/256, 256>>>(iW2, 0, 4, 256, 4);   // g_mw2

    long long totz = (long long)M_SEG * PHSTR / 2 + M_SEG;
    k_zero<<<(unsigned)((totz + 255)/256), 256>>>();

    float* out_frac = nullptr;
    if ((long long)out_size >= (long long)N_ROWS * (LAT + 1))
        out_frac = out + (size_t)N_ROWS * LAT;
    long long tota = (long long)N_ROWS * 17;
    k_accum<<<(unsigned)((tota + 255)/256), 256>>>(emb, frac, seg, out_frac);

    k_mix<<<(M_SEG + 63)/64, 256, SMEM_TOTAL>>>(iW1, ib1, ib2);
    k_gate<<<N_ROWS / 64, 256, SMEM_TOTAL>>>(emb, frac, seg, gW1, gb1, gb2, out);
}

// round 16
// speedup vs baseline: 1.7856x; 1.0290x over previous
#include <cuda_runtime.h>
#include <cuda_fp16.h>
#include <cstdint>
#include <math.h>

#define N_ROWS 400000
#define M_SEG  100000
#define EMB    128
#define CTX    256
#define LAT    256
#define PHSTR  136           // pooled row stride in halves

#define CHW 18432            // halves per 64-wide B chunk image (256 x 72 = 36864 B)
#define ASTR1 144            // A1 row stride bytes
#define ASTR2 528            // A2 row stride bytes

// smem layout (bytes) — total 109KB -> 2 CTAs/SM
#define OFF_B1S   0          // bias1: 256 f32
#define OFF_B2S   1024       // bias2: 256 f32
#define OFF_AUX   2048       // axseg/axinv: 64 x 4B
#define OFF_FRS   2560       // per-row scalar: 64 f32
#define OFF_WFR   3072       // rank-1 weight row: 256 f32 -> 4096
#define OFF_A2    4096       // A2: 64 x 528B = 33792 -> 37888
#define OFF_A10   4096       // A1 buf0 (aliases A2 lower): 64 x 144 = 9216
#define OFF_A11   13312      // A1 buf1 (aliases A2 upper): 9216 -> 22528
#define OFF_BB0   37888      // B buf0: 36864 -> 74752
#define OFF_BB1   74752      // B buf1: 36864 -> 111616
#define SMEM_TOTAL 111616

// scratch globals
__device__ __align__(16) __half g_pooled[(size_t)M_SEG * PHSTR];
__device__ float g_counts[M_SEG];
__device__ float g_ctxpre[(size_t)M_SEG * CTX];   // ctx @ gW1[129:385], fp32
// prepped B chunk images: [chunk][256][72] fp16 RN
__device__ __align__(16) __half g_gwe[2*CHW];   // gate W1 rows 0..127
__device__ __align__(16) __half g_gwc[4*CHW];   // gate W1 rows 129..384
__device__ __align__(16) __half g_gw2[4*CHW];
__device__ __align__(16) __half g_mw1[2*CHW];   // iW1 rows 0..127 (row 128 -> rank-1 epi)
__device__ __align__(16) __half g_mw2[4*CHW];

__device__ __forceinline__ uint32_t smem_u32(const void* p) {
    uint32_t a;
    asm("{ .reg .u64 t; cvta.to.shared.u64 t, %1; cvt.u32.u64 %0, t; }" : "=r"(a) : "l"(p));
    return a;
}
#define LDSM4(r0,r1,r2,r3,addr) \
    asm volatile("ldmatrix.sync.aligned.m8n8.x4.shared.b16 {%0,%1,%2,%3}, [%4];" \
        : "=r"(r0),"=r"(r1),"=r"(r2),"=r"(r3) : "r"(addr))
#define MMA(d,a,b0,b1) \
    asm volatile("mma.sync.aligned.m16n8k16.row.col.f32.f16.f16.f32 " \
        "{%0,%1,%2,%3},{%4,%5,%6,%7},{%8,%9},{%0,%1,%2,%3};" \
        : "+f"((d)[0]),"+f"((d)[1]),"+f"((d)[2]),"+f"((d)[3]) \
        : "r"((a)[0]),"r"((a)[1]),"r"((a)[2]),"r"((a)[3]),"r"(b0),"r"(b1))
#define CP16(sa,gp) asm volatile("cp.async.cg.shared.global [%0], [%1], 16;" :: "r"(sa),"l"(gp))
#define CP_COMMIT() asm volatile("cp.async.commit_group;" ::: "memory")
#define CP_WAIT0()  asm volatile("cp.async.wait_group 0;" ::: "memory")
#define STS32(a,v)  asm volatile("st.shared.b32 [%0], %1;" :: "r"(a),"r"(v) : "memory")
#define STSV2(a,x,y) asm volatile("st.shared.v2.b32 [%0], {%1,%2};" :: "r"(a),"r"(x),"r"(y) : "memory")
#define REDH2V4(p,a,b,c,d) \
    asm volatile("red.global.add.noftz.v4.f16x2 [%0], {%1,%2,%3,%4};" \
        :: "l"(p), "r"(a), "r"(b), "r"(c), "r"(d) : "memory")
#define REDH2(p,a) \
    asm volatile("red.global.add.noftz.f16x2 [%0], %1;" :: "l"(p), "r"(a) : "memory")

__device__ __forceinline__ float sp(float x) {
    return fmaxf(x, 0.f) + __logf(1.f + __expf(-fabsf(x)));
}
__device__ __forceinline__ uint32_t pack2h(float a, float b) {
    __half2 h = __floats2half2_rn(a, b);
    return *(uint32_t*)&h;
}

// ---------------------------------------------------------------------------
// merged: zero g_pooled/g_counts AND build all 16 weight chunk images.
// chunk map: [0,2)=gwe(gW1,m0,K128)  [2,6)=gwc(gW1,m2)  [6,10)=gw2(gW2,m0,K256)
//            [10,12)=mw1(iW1,m0,K128)  [12,16)=mw2(iW2,m0,K256)
__global__ void k_prepzero(const float* __restrict__ gW1, const float* __restrict__ gW2,
                           const float* __restrict__ iW1, const float* __restrict__ iW2) {
    long long idx = (long long)blockIdx.x * 256 + threadIdx.x;
    const long long P = (long long)M_SEG * PHSTR / 2;   // u32 words
    if (idx < P) ((uint32_t*)g_pooled)[idx] = 0u;
    else if (idx < P + M_SEG) g_counts[idx - P] = 0.f;

    if (idx >= 16LL * CHW) return;
    int which = (int)(idx / CHW);
    int rem = (int)(idx - (long long)which * CHW);
    int n = rem / 72, kk = rem - n * 72;

    const float* W; __half* dst; int base, mode, Kreal;
    if (which < 2)       { W = gW1; dst = g_gwe; base = 0;  mode = 0; Kreal = 128; }
    else if (which < 6)  { W = gW1; dst = g_gwc; base = 2;  mode = 2; Kreal = 256; }
    else if (which < 10) { W = gW2; dst = g_gw2; base = 6;  mode = 0; Kreal = 256; }
    else if (which < 12) { W = iW1; dst = g_mw1; base = 10; mode = 0; Kreal = 128; }
    else                 { W = iW2; dst = g_mw2; base = 12; mode = 0; Kreal = 256; }

    int cl = which - base;
    float v = 0.f;
    if (kk < 64) {
        int kg = cl * 64 + kk, sr;
        if (mode == 2) sr = (kg < 256) ? kg + 129 : -1;
        else           sr = (kg < Kreal) ? kg : -1;
        if (sr >= 0) v = W[(long long)sr * 256 + n];
    }
    dst[(long long)cl * CHW + rem] = __float2half_rn(v);
}

__global__ void k_accum(const float* __restrict__ emb, const float* __restrict__ frac,
                        const int* __restrict__ seg, float* __restrict__ out_frac) {
    int idx = blockIdx.x * 256 + threadIdx.x;
    if (idx >= N_ROWS * 17) return;
    int r = idx / 17;
    int g = idx - r * 17;
    int s = seg[r];
    if (g < 16) {
        const float4* e = (const float4*)&emb[(long long)r * EMB + g * 8];
        float4 a = e[0], b = e[1];
        REDH2V4(&g_pooled[(size_t)s * PHSTR + g * 8],
                pack2h(a.x, a.y), pack2h(a.z, a.w),
                pack2h(b.x, b.y), pack2h(b.z, b.w));
    } else {
        float f = frac[r];
        REDH2(&g_pooled[(size_t)s * PHSTR + 128], pack2h(f, 0.f));
        atomicAdd(&g_counts[s], 1.f);
        if (out_frac) out_frac[r] = f;
    }
}

// ---------------------------------------------------------------------------
__device__ __forceinline__ void cp_chunk(uint32_t dst, const __half* src, int c, int tid) {
    const uint4* gp = (const uint4*)src + (long long)c * (CHW / 8);
#pragma unroll
    for (int j = 0; j < 9; j++) {
        int i = tid + j * 256;
        CP16(dst + i * 16, gp + i);
    }
}

// fp16 MMA over one 64-wide K chunk; warp tile 32x64; B stride 144B
__device__ __forceinline__ void mma_chunk(float (&acc)[2][8][4],
                                          uint32_t aBase, int aStride,
                                          uint32_t bBase,
                                          int lane, int m0, int n0w) {
    const int arow = (lane & 7) + ((lane >> 3) & 1) * 8;
    const int brow = (lane & 7) + (lane >> 4) * 8;
    const int bk0  = ((lane >> 3) & 1) * 16;
#pragma unroll
    for (int ks = 0; ks < 4; ks++) {
        uint32_t ah[2][4];
        int akb = ks * 32 + (lane >> 4) * 16;
#pragma unroll
        for (int mi = 0; mi < 2; mi++) {
            uint32_t ra = aBase + (uint32_t)(m0 + mi * 16 + arow) * aStride + akb;
            LDSM4(ah[mi][0], ah[mi][1], ah[mi][2], ah[mi][3], ra);
        }
        int bkb = ks * 32 + bk0;
#pragma unroll
        for (int g = 0; g < 4; g++) {
            uint32_t bh[4];
            uint32_t ro = (uint32_t)(n0w + g * 16 + brow) * 144 + bkb;
            LDSM4(bh[0], bh[1], bh[2], bh[3], bBase + ro);
#pragma unroll
            for (int mi = 0; mi < 2; mi++) {
                MMA(acc[mi][2*g],   ah[mi], bh[0], bh[1]);
                MMA(acc[mi][2*g+1], ah[mi], bh[2], bh[3]);
            }
        }
    }
}

#define CLR_ACC() \
    _Pragma("unroll") for (int i_ = 0; i_ < 2; i_++) \
    _Pragma("unroll") for (int j_ = 0; j_ < 8; j_++) \
    _Pragma("unroll") for (int q_ = 0; q_ < 4; q_++) acc[i_][j_][q_] = 0.f

// ---------------------------------------------------------------------------
// mix: pooled mean L1 (2 chunks) + frac rank-1 epi -> L2 (4) -> ctx -> L3 (4)
//      -> g_ctxpre (fp32).  Tile 64x256, 2 CTAs/SM.
__global__ __launch_bounds__(256, 2)
void k_mix(const float* __restrict__ iW1,
           const float* __restrict__ b1v, const float* __restrict__ b2v) {
    extern __shared__ __align__(16) char sm[];
    const uint32_t sb = smem_u32(sm);
    const int tid = threadIdx.x, w = tid >> 5, lane = tid & 31;
    const int m0 = (w & 1) * 32, n0w = (w >> 1) * 64;
    const int rowBase = blockIdx.x * 64;

    float* bias1s = (float*)(sm + OFF_B1S);
    float* bias2s = (float*)(sm + OFF_B2S);
    float* axinv  = (float*)(sm + OFF_AUX);
    float* pfs    = (float*)(sm + OFF_FRS);
    float* wfr    = (float*)(sm + OFF_WFR);

    bias1s[tid] = b1v[tid];
    bias2s[tid] = b2v[tid];
    wfr[tid]    = iW1[128 * 256 + tid];
    if (tid < 64) {
        int gr = rowBase + tid;
        float c = (gr < M_SEG) ? g_counts[gr] : 1.f;
        float inv = 1.f / fmaxf(c, 1.f);
        axinv[tid] = inv;
        pfs[tid] = (gr < M_SEG)
            ? __half2float(g_pooled[(size_t)gr * PHSTR + 128]) * inv : 0.f;
    }
    __syncthreads();

    const int gr_ = tid >> 2, gq = tid & 3;   // 4 threads per row, 16 cols each
    const int rg = rowBase + gr_;
    const int kk0 = gq * 16;
    auto gather = [&](int c, uint32_t (&ar)[8]) {
        float inv = axinv[gr_];
#pragma unroll
        for (int i = 0; i < 4; i++) {
            int k = c * 64 + kk0 + i * 4;
            float4 v = make_float4(0.f, 0.f, 0.f, 0.f);
            if (rg < M_SEG) {
                const __half2* hp = (const __half2*)&g_pooled[(size_t)rg * PHSTR + k];
                float2 f01 = __half22float2(hp[0]), f23 = __half22float2(hp[1]);
                v = make_float4(f01.x * inv, f01.y * inv, f23.x * inv, f23.y * inv);
            }
            ar[2*i]   = pack2h(v.x, v.y);
            ar[2*i+1] = pack2h(v.z, v.w);
        }
    };
    auto stsA = [&](uint32_t abuf, const uint32_t (&ar)[8]) {
        uint32_t base = abuf + (uint32_t)gr_ * ASTR1 + (uint32_t)kk0 * 2;
#pragma unroll
        for (int i = 0; i < 4; i++)
            STSV2(base + i * 8, ar[2*i], ar[2*i+1]);
    };

    float acc[2][8][4];
    CLR_ACC();
    const int rb = m0 + (lane >> 2);
    const int cb = n0w + (lane & 3) * 2;

    // -------- L1: 2 chunks --------
    {
        uint32_t ar[8];
        gather(0, ar); stsA(sb + OFF_A10, ar);
        cp_chunk(sb + OFF_BB0, g_mw1, 0, tid); CP_COMMIT();
    }
    for (int c = 0; c < 2; ++c) {
        uint32_t ar[8];
        if (c + 1 < 2) gather(c + 1, ar);
        CP_WAIT0();
        __syncthreads();
        if (c + 1 < 2) { cp_chunk(sb + OFF_BB1, g_mw1, 1, tid); CP_COMMIT(); }
        mma_chunk(acc, sb + ((c & 1) ? OFF_A11 : OFF_A10), ASTR1,
                  sb + ((c & 1) ? OFF_BB1 : OFF_BB0), lane, m0, n0w);
        if (c + 1 < 2) stsA(sb + OFF_A11, ar);
    }
    __syncthreads();   // all A1 reads done before epi1 writes A2 (aliased)
    cp_chunk(sb + OFF_BB0, g_mw2, 0, tid); CP_COMMIT();   // L2 chunk0 -> BB0

    // epi1: + pf*wfr + b1 -> softplus -> A2 (fp16)
    {
        float pf[4];
#pragma unroll
        for (int q = 0; q < 4; q++)
            pf[q] = pfs[rb + (q >> 1) * 16 + (q & 1) * 8];
#pragma unroll
        for (int mi = 0; mi < 2; mi++)
#pragma unroll
            for (int ni = 0; ni < 8; ni++) {
                int col = cb + ni * 8;
                float2 bb = *(float2*)&bias1s[col];
                float2 wf = *(float2*)&wfr[col];
                int row = rb + mi * 16;
                uint32_t ad = sb + OFF_A2 + (uint32_t)row * ASTR2 + (uint32_t)col * 2;
                STS32(ad, pack2h(sp(acc[mi][ni][0] + pf[mi*2]*wf.x + bb.x),
                                 sp(acc[mi][ni][1] + pf[mi*2]*wf.y + bb.y)));
                STS32(ad + 8*ASTR2, pack2h(sp(acc[mi][ni][2] + pf[mi*2+1]*wf.x + bb.x),
                                           sp(acc[mi][ni][3] + pf[mi*2+1]*wf.y + bb.y)));
            }
    }
    CLR_ACC();

    // -------- L2: 4 chunks (cur = c&1 ? BB1 : BB0) --------
    for (int c = 0; c < 4; ++c) {
        CP_WAIT0();
        __syncthreads();
        if (c + 1 < 4) { cp_chunk(sb + (((c+1)&1)?OFF_BB1:OFF_BB0), g_mw2, c+1, tid); CP_COMMIT(); }
        else           { cp_chunk(sb + OFF_BB0, g_gwc, 0, tid); CP_COMMIT(); }  // c=3 cur=BB1, BB0 free
        mma_chunk(acc, sb + OFF_A2 + (uint32_t)c * 128, ASTR2,
                  sb + ((c&1)?OFF_BB1:OFF_BB0), lane, m0, n0w);
    }
    __syncthreads();   // all A2 reads done before epi2 rewrites A2

    // epi2 -> ctx fp16 in A2
#pragma unroll
    for (int mi = 0; mi < 2; mi++)
#pragma unroll
        for (int ni = 0; ni < 8; ni++) {
            int col = cb + ni * 8;
            float2 bb = *(float2*)&bias2s[col];
            int row = rb + mi * 16;
            uint32_t ad = sb + OFF_A2 + (uint32_t)row * ASTR2 + (uint32_t)col * 2;
            STS32(ad, pack2h(sp(acc[mi][ni][0]+bb.x), sp(acc[mi][ni][1]+bb.y)));
            STS32(ad + 8*ASTR2, pack2h(sp(acc[mi][ni][2]+bb.x), sp(acc[mi][ni][3]+bb.y)));
        }
    CLR_ACC();

    // -------- L3: 4 chunks (cur = c&1 ? BB1 : BB0; chunk0 in BB0) --------
    for (int c = 0; c < 4; ++c) {
        CP_WAIT0();
        __syncthreads();
        if (c + 1 < 4) { cp_chunk(sb + (((c+1)&1)?OFF_BB1:OFF_BB0), g_gwc, c+1, tid); CP_COMMIT(); }
        mma_chunk(acc, sb + OFF_A2 + (uint32_t)c * 128, ASTR2,
                  sb + ((c&1)?OFF_BB1:OFF_BB0), lane, m0, n0w);
    }

    // epi3 -> g_ctxpre (fp32)
#pragma unroll
    for (int mi = 0; mi < 2; mi++)
#pragma unroll
        for (int ni = 0; ni < 8; ni++) {
            int col = cb + ni * 8;
            int gr = rowBase + rb + mi * 16;
            if (gr < M_SEG)
                *(float2*)&g_ctxpre[(size_t)gr * 256 + col] =
                    make_float2(acc[mi][ni][0], acc[mi][ni][1]);
            if (gr + 8 < M_SEG)
                *(float2*)&g_ctxpre[(size_t)(gr+8) * 256 + col] =
                    make_float2(acc[mi][ni][2], acc[mi][ni][3]);
        }
}

// ---------------------------------------------------------------------------
// gate: emb L1 (2 chunks) + ctxpre[seg] + frac*w128 epi -> L2 (4) -> out
//       Tile 64x256, 2 CTAs/SM.
__global__ __launch_bounds__(256, 2)
void k_gate(const float* __restrict__ emb, const float* __restrict__ frac,
            const int* __restrict__ seg, const float* __restrict__ gW1,
            const float* __restrict__ b1v, const float* __restrict__ b2v,
            float* __restrict__ outp) {
    extern __shared__ __align__(16) char sm[];
    const uint32_t sb = smem_u32(sm);
    const int tid = threadIdx.x, w = tid >> 5, lane = tid & 31;
    const int m0 = (w & 1) * 32, n0w = (w >> 1) * 64;
    const int rowBase = blockIdx.x * 64;

    float* bias1s = (float*)(sm + OFF_B1S);
    float* bias2s = (float*)(sm + OFF_B2S);
    int*   axseg  = (int*)  (sm + OFF_AUX);
    float* fracs  = (float*)(sm + OFF_FRS);
    float* wfrac  = (float*)(sm + OFF_WFR);

    bias1s[tid] = b1v[tid];
    bias2s[tid] = b2v[tid];
    wfrac[tid]  = gW1[128 * 256 + tid];
    if (tid < 64) {
        axseg[tid] = seg[rowBase + tid];
        fracs[tid] = frac[rowBase + tid];
    }

    const int gr_ = tid >> 2, gq = tid & 3;
    const long long rg = rowBase + gr_;
    const int kk0 = gq * 16;
    auto gatherE = [&](int c, uint32_t (&ar)[8]) {
#pragma unroll
        for (int i = 0; i < 4; i++) {
            float4 v = *(const float4*)&emb[rg * EMB + c * 64 + kk0 + i * 4];
            ar[2*i]   = pack2h(v.x, v.y);
            ar[2*i+1] = pack2h(v.z, v.w);
        }
    };
    auto stsA = [&](uint32_t abuf, const uint32_t (&ar)[8]) {
        uint32_t base = abuf + (uint32_t)gr_ * ASTR1 + (uint32_t)kk0 * 2;
#pragma unroll
        for (int i = 0; i < 4; i++)
            STSV2(base + i * 8, ar[2*i], ar[2*i+1]);
    };

    float acc[2][8][4];
    CLR_ACC();
    const int rb = m0 + (lane >> 2);
    const int cb = n0w + (lane & 3) * 2;

    // -------- L1: 2 chunks --------
    {
        uint32_t ar[8];
        gatherE(0, ar); stsA(sb + OFF_A10, ar);
        cp_chunk(sb + OFF_BB0, g_gwe, 0, tid); CP_COMMIT();
    }
    for (int c = 0; c < 2; ++c) {
        uint32_t ar[8];
        if (c + 1 < 2) gatherE(c + 1, ar);
        CP_WAIT0();
        __syncthreads();    // also makes axseg/fracs/bias visible (first iter)
        if (c + 1 < 2) { cp_chunk(sb + OFF_BB1, g_gwe, 1, tid); CP_COMMIT(); }
        mma_chunk(acc, sb + ((c & 1) ? OFF_A11 : OFF_A10), ASTR1,
                  sb + ((c & 1) ? OFF_BB1 : OFF_BB0), lane, m0, n0w);
        if (c + 1 < 2) stsA(sb + OFF_A11, ar);
    }
    __syncthreads();   // A1 reads done before epi1 writes A2 (aliased)
    cp_chunk(sb + OFF_BB0, g_gw2, 0, tid); CP_COMMIT();   // L2 chunk0 -> BB0

    // epi1: acc += ctxpre[seg] + frac*wfrac + b1 -> softplus -> A2
    {
        int sgl[4]; float fr[4];
#pragma unroll
        for (int q = 0; q < 4; q++) {
            int row = rb + (q >> 1) * 16 + (q & 1) * 8;
            sgl[q] = axseg[row];
            fr[q]  = fracs[row];
        }
#pragma unroll
        for (int mi = 0; mi < 2; mi++)
#pragma unroll
            for (int ni = 0; ni < 8; ni++) {
                int col = cb + ni * 8;
                float2 bb = *(float2*)&bias1s[col];
                float2 wf = *(float2*)&wfrac[col];
                float2 c0 = *(const float2*)&g_ctxpre[(size_t)sgl[mi*2]   * 256 + col];
                float2 c1 = *(const float2*)&g_ctxpre[(size_t)sgl[mi*2+1] * 256 + col];
                int row = rb + mi * 16;
                uint32_t ad = sb + OFF_A2 + (uint32_t)row * ASTR2 + (uint32_t)col * 2;
                STS32(ad, pack2h(sp(acc[mi][ni][0] + c0.x + fr[mi*2]*wf.x + bb.x),
                                 sp(acc[mi][ni][1] + c0.y + fr[mi*2]*wf.y + bb.y)));
                STS32(ad + 8*ASTR2, pack2h(sp(acc[mi][ni][2] + c1.x + fr[mi*2+1]*wf.x + bb.x),
                                           sp(acc[mi][ni][3] + c1.y + fr[mi*2+1]*wf.y + bb.y)));
            }
    }
    CLR_ACC();

    // -------- L2: 4 chunks (cur = c&1 ? BB1 : BB0) --------
    for (int c = 0; c < 4; ++c) {
        CP_WAIT0();
        __syncthreads();   // iter0: epi1 STS visible
        if (c + 1 < 4) { cp_chunk(sb + (((c+1)&1)?OFF_BB1:OFF_BB0), g_gw2, c+1, tid); CP_COMMIT(); }
        mma_chunk(acc, sb + OFF_A2 + (uint32_t)c * 128, ASTR2,
                  sb + ((c&1)?OFF_BB1:OFF_BB0), lane, m0, n0w);
    }

    // epi2 -> out
#pragma unroll
    for (int mi = 0; mi < 2; mi++)
#pragma unroll
        for (int ni = 0; ni < 8; ni++) {
            int col = cb + ni * 8;
            float2 bb = *(float2*)&bias2s[col];
            int gr = rowBase + rb + mi * 16;
            *(float2*)&outp[(long long)gr * 256 + col] =
                make_float2(sp(acc[mi][ni][0]+bb.x), sp(acc[mi][ni][1]+bb.y));
            *(float2*)&outp[(long long)(gr+8) * 256 + col] =
                make_float2(sp(acc[mi][ni][2]+bb.x), sp(acc[mi][ni][3]+bb.y));
        }
}

// ---------------------------------------------------------------------------
extern "C" void kernel_launch(void* const* d_in, const int* in_sizes, int n_in,
                              void* d_out, int out_size) {
    const float* emb  = (const float*)d_in[0];
    const float* frac = (const float*)d_in[1];
    const int*   seg  = (const int*)  d_in[2];
    const float* iW1  = (const float*)d_in[3];
    const float* ib1  = (const float*)d_in[4];
    const float* iW2  = (const float*)d_in[5];
    const float* ib2  = (const float*)d_in[6];
    const float* gW1  = (const float*)d_in[7];
    const float* gb1  = (const float*)d_in[8];
    const float* gW2  = (const float*)d_in[9];
    const float* gb2  = (const float*)d_in[10];
    float* out = (float*)d_out;

    cudaFuncSetAttribute(k_mix,  cudaFuncAttributeMaxDynamicSharedMemorySize, SMEM_TOTAL);
    cudaFuncSetAttribute(k_gate, cudaFuncAttributeMaxDynamicSharedMemorySize, SMEM_TOTAL);

    // launch 1: merged prep + zero (covers max(16*CHW, pooled words + counts))
    long long totz = (long long)M_SEG * PHSTR / 2 + M_SEG;
    long long totp = 16LL * CHW;
    long long tot1 = totz > totp ? totz : totp;
    k_prepzero<<<(unsigned)((tot1 + 255) / 256), 256>>>(gW1, gW2, iW1, iW2);

    // launch 2: segment accumulate
    float* out_frac = nullptr;
    if ((long long)out_size >= (long long)N_ROWS * (LAT + 1))
        out_frac = out + (size_t)N_ROWS * LAT;
    long long tota = (long long)N_ROWS * 17;
    k_accum<<<(unsigned)((tota + 255) / 256), 256>>>(emb, frac, seg, out_frac);

    // launch 3: mixture MLP (+ hoisted ctx GEMM)
    k_mix<<<(M_SEG + 63)/64, 256, SMEM_TOTAL>>>(iW1, ib1, ib2);

    // launch 4: gate MLP (profiled by ncu -s/-c)
    k_gate<<<N_ROWS / 64, 256, SMEM_TOTAL>>>(emb, frac, seg, gW1, gb1, gb2, out);
}

// round 17
// speedup vs baseline: 1.8574x; 1.0402x over previous
#include <cuda_runtime.h>
#include <cuda_fp16.h>
#include <cstdint>
#include <math.h>

#define N_ROWS 400000
#define M_SEG  100000
#define EMB    128
#define CTX    256
#define LAT    256
#define PHSTR  136           // pooled row stride in halves

#define CHW 18432            // halves per 64-wide B chunk image (256 x 72 = 36864 B)
#define ASTR1 144            // A1 row stride bytes
#define ASTR2 528            // A2 row stride bytes
#define CXSTR 528            // ctxpre smem row stride bytes (64 rows -> 33792 <= 36864)

// smem layout (bytes) — total 109KB -> 2 CTAs/SM
#define OFF_B1S   0          // bias1: 256 f32
#define OFF_B2S   1024       // bias2: 256 f32
#define OFF_AUX   2048       // axinv: 64 x 4B (mix)
#define OFF_FRS   2560       // per-row scalar: 64 f32
#define OFF_WFR   3072       // rank-1 weight row: 256 f32 -> 4096
#define OFF_A2    4096       // A2: 64 x 528B = 33792 -> 37888
#define OFF_A10   4096       // A1 buf0 (aliases A2 lower): 64 x 144 = 9216
#define OFF_A11   13312      // A1 buf1 (aliases A2 upper): 9216 -> 22528
#define OFF_BB0   37888      // B buf0: 36864 -> 74752
#define OFF_BB1   74752      // B buf1 / ctxpre tile: 36864 -> 111616
#define SMEM_TOTAL 111616

// scratch globals
__device__ __align__(16) __half g_pooled[(size_t)M_SEG * PHSTR];
__device__ float g_counts[M_SEG];
__device__ __align__(16) __half g_ctxpre[(size_t)M_SEG * CTX];  // ctx @ gW1[129:385], fp16
// prepped B chunk images: [chunk][256][72] fp16 RN
__device__ __align__(16) __half g_gwe[2*CHW];   // gate W1 rows 0..127
__device__ __align__(16) __half g_gwc[4*CHW];   // gate W1 rows 129..384
__device__ __align__(16) __half g_gw2[4*CHW];
__device__ __align__(16) __half g_mw1[2*CHW];   // iW1 rows 0..127 (row 128 -> rank-1 epi)
__device__ __align__(16) __half g_mw2[4*CHW];

__device__ __forceinline__ uint32_t smem_u32(const void* p) {
    uint32_t a;
    asm("{ .reg .u64 t; cvta.to.shared.u64 t, %1; cvt.u32.u64 %0, t; }" : "=r"(a) : "l"(p));
    return a;
}
#define LDSM4(r0,r1,r2,r3,addr) \
    asm volatile("ldmatrix.sync.aligned.m8n8.x4.shared.b16 {%0,%1,%2,%3}, [%4];" \
        : "=r"(r0),"=r"(r1),"=r"(r2),"=r"(r3) : "r"(addr))
#define MMA(d,a,b0,b1) \
    asm volatile("mma.sync.aligned.m16n8k16.row.col.f32.f16.f16.f32 " \
        "{%0,%1,%2,%3},{%4,%5,%6,%7},{%8,%9},{%0,%1,%2,%3};" \
        : "+f"((d)[0]),"+f"((d)[1]),"+f"((d)[2]),"+f"((d)[3]) \
        : "r"((a)[0]),"r"((a)[1]),"r"((a)[2]),"r"((a)[3]),"r"(b0),"r"(b1))
#define CP16(sa,gp) asm volatile("cp.async.cg.shared.global [%0], [%1], 16;" :: "r"(sa),"l"(gp))
#define CP_COMMIT() asm volatile("cp.async.commit_group;" ::: "memory")
#define CP_WAIT0()  asm volatile("cp.async.wait_group 0;" ::: "memory")
#define CP_WAIT1()  asm volatile("cp.async.wait_group 1;" ::: "memory")
#define STS32(a,v)  asm volatile("st.shared.b32 [%0], %1;" :: "r"(a),"r"(v) : "memory")
#define LDSH2(h,a)  asm volatile("ld.shared.b32 %0, [%1];" : "=r"(h) : "r"(a))
#define STSV2(a,x,y) asm volatile("st.shared.v2.b32 [%0], {%1,%2};" :: "r"(a),"r"(x),"r"(y) : "memory")
#define REDH2V4(p,a,b,c,d) \
    asm volatile("red.global.add.noftz.v4.f16x2 [%0], {%1,%2,%3,%4};" \
        :: "l"(p), "r"(a), "r"(b), "r"(c), "r"(d) : "memory")
#define REDH2(p,a) \
    asm volatile("red.global.add.noftz.f16x2 [%0], %1;" :: "l"(p), "r"(a) : "memory")

__device__ __forceinline__ float sp(float x) {
    return fmaxf(x, 0.f) + __logf(1.f + __expf(-fabsf(x)));
}
__device__ __forceinline__ uint32_t pack2h(float a, float b) {
    __half2 h = __floats2half2_rn(a, b);
    return *(uint32_t*)&h;
}
__device__ __forceinline__ float2 lds_h2f(uint32_t addr) {
    uint32_t u; LDSH2(u, addr);
    return __half22float2(*(__half2*)&u);
}

// ---------------------------------------------------------------------------
// merged: zero g_pooled/g_counts AND build all 16 weight chunk images.
__global__ void k_prepzero(const float* __restrict__ gW1, const float* __restrict__ gW2,
                           const float* __restrict__ iW1, const float* __restrict__ iW2) {
    long long idx = (long long)blockIdx.x * 256 + threadIdx.x;
    const long long P = (long long)M_SEG * PHSTR / 2;   // u32 words
    if (idx < P) ((uint32_t*)g_pooled)[idx] = 0u;
    else if (idx < P + M_SEG) g_counts[idx - P] = 0.f;

    if (idx >= 16LL * CHW) return;
    int which = (int)(idx / CHW);
    int rem = (int)(idx - (long long)which * CHW);
    int n = rem / 72, kk = rem - n * 72;

    const float* W; __half* dst; int base, mode, Kreal;
    if (which < 2)       { W = gW1; dst = g_gwe; base = 0;  mode = 0; Kreal = 128; }
    else if (which < 6)  { W = gW1; dst = g_gwc; base = 2;  mode = 2; Kreal = 256; }
    else if (which < 10) { W = gW2; dst = g_gw2; base = 6;  mode = 0; Kreal = 256; }
    else if (which < 12) { W = iW1; dst = g_mw1; base = 10; mode = 0; Kreal = 128; }
    else                 { W = iW2; dst = g_mw2; base = 12; mode = 0; Kreal = 256; }

    int cl = which - base;
    float v = 0.f;
    if (kk < 64) {
        int kg = cl * 64 + kk, sr;
        if (mode == 2) sr = (kg < 256) ? kg + 129 : -1;
        else           sr = (kg < Kreal) ? kg : -1;
        if (sr >= 0) v = W[(long long)sr * 256 + n];
    }
    dst[(long long)cl * CHW + rem] = __float2half_rn(v);
}

__global__ void k_accum(const float* __restrict__ emb, const float* __restrict__ frac,
                        const int* __restrict__ seg, float* __restrict__ out_frac) {
    int idx = blockIdx.x * 256 + threadIdx.x;
    if (idx >= N_ROWS * 17) return;
    int r = idx / 17;
    int g = idx - r * 17;
    int s = seg[r];
    if (g < 16) {
        const float4* e = (const float4*)&emb[(long long)r * EMB + g * 8];
        float4 a = e[0], b = e[1];
        REDH2V4(&g_pooled[(size_t)s * PHSTR + g * 8],
                pack2h(a.x, a.y), pack2h(a.z, a.w),
                pack2h(b.x, b.y), pack2h(b.z, b.w));
    } else {
        float f = frac[r];
        REDH2(&g_pooled[(size_t)s * PHSTR + 128], pack2h(f, 0.f));
        atomicAdd(&g_counts[s], 1.f);
        if (out_frac) out_frac[r] = f;
    }
}

// ---------------------------------------------------------------------------
__device__ __forceinline__ void cp_chunk(uint32_t dst, const __half* src, int c, int tid) {
    const uint4* gp = (const uint4*)src + (long long)c * (CHW / 8);
#pragma unroll
    for (int j = 0; j < 9; j++) {
        int i = tid + j * 256;
        CP16(dst + i * 16, gp + i);
    }
}

// fp16 MMA over one 64-wide K chunk; warp tile 32x64; B stride 144B
__device__ __forceinline__ void mma_chunk(float (&acc)[2][8][4],
                                          uint32_t aBase, int aStride,
                                          uint32_t bBase,
                                          int lane, int m0, int n0w) {
    const int arow = (lane & 7) + ((lane >> 3) & 1) * 8;
    const int brow = (lane & 7) + (lane >> 4) * 8;
    const int bk0  = ((lane >> 3) & 1) * 16;
#pragma unroll
    for (int ks = 0; ks < 4; ks++) {
        uint32_t ah[2][4];
        int akb = ks * 32 + (lane >> 4) * 16;
#pragma unroll
        for (int mi = 0; mi < 2; mi++) {
            uint32_t ra = aBase + (uint32_t)(m0 + mi * 16 + arow) * aStride + akb;
            LDSM4(ah[mi][0], ah[mi][1], ah[mi][2], ah[mi][3], ra);
        }
        int bkb = ks * 32 + bk0;
#pragma unroll
        for (int g = 0; g < 4; g++) {
            uint32_t bh[4];
            uint32_t ro = (uint32_t)(n0w + g * 16 + brow) * 144 + bkb;
            LDSM4(bh[0], bh[1], bh[2], bh[3], bBase + ro);
#pragma unroll
            for (int mi = 0; mi < 2; mi++) {
                MMA(acc[mi][2*g],   ah[mi], bh[0], bh[1]);
                MMA(acc[mi][2*g+1], ah[mi], bh[2], bh[3]);
            }
        }
    }
}

#define CLR_ACC() \
    _Pragma("unroll") for (int i_ = 0; i_ < 2; i_++) \
    _Pragma("unroll") for (int j_ = 0; j_ < 8; j_++) \
    _Pragma("unroll") for (int q_ = 0; q_ < 4; q_++) acc[i_][j_][q_] = 0.f

// ---------------------------------------------------------------------------
// mix: pooled mean L1 (2 chunks) + frac rank-1 epi -> L2 (4) -> ctx -> L3 (4)
//      -> g_ctxpre (fp16).  Tile 64x256, 2 CTAs/SM.
__global__ __launch_bounds__(256, 2)
void k_mix(const float* __restrict__ iW1,
           const float* __restrict__ b1v, const float* __restrict__ b2v) {
    extern __shared__ __align__(16) char sm[];
    const uint32_t sb = smem_u32(sm);
    const int tid = threadIdx.x, w = tid >> 5, lane = tid & 31;
    const int m0 = (w & 1) * 32, n0w = (w >> 1) * 64;
    const int rowBase = blockIdx.x * 64;

    float* bias1s = (float*)(sm + OFF_B1S);
    float* bias2s = (float*)(sm + OFF_B2S);
    float* axinv  = (float*)(sm + OFF_AUX);
    float* pfs    = (float*)(sm + OFF_FRS);
    float* wfr    = (float*)(sm + OFF_WFR);

    bias1s[tid] = b1v[tid];
    bias2s[tid] = b2v[tid];
    wfr[tid]    = iW1[128 * 256 + tid];
    if (tid < 64) {
        int gr = rowBase + tid;
        float c = (gr < M_SEG) ? g_counts[gr] : 1.f;
        float inv = 1.f / fmaxf(c, 1.f);
        axinv[tid] = inv;
        pfs[tid] = (gr < M_SEG)
            ? __half2float(g_pooled[(size_t)gr * PHSTR + 128]) * inv : 0.f;
    }
    __syncthreads();

    const int gr_ = tid >> 2, gq = tid & 3;   // 4 threads per row, 16 cols each
    const int rg = rowBase + gr_;
    const int kk0 = gq * 16;
    auto gather = [&](int c, uint32_t (&ar)[8]) {
        float inv = axinv[gr_];
#pragma unroll
        for (int i = 0; i < 4; i++) {
            int k = c * 64 + kk0 + i * 4;
            float4 v = make_float4(0.f, 0.f, 0.f, 0.f);
            if (rg < M_SEG) {
                const __half2* hp = (const __half2*)&g_pooled[(size_t)rg * PHSTR + k];
                float2 f01 = __half22float2(hp[0]), f23 = __half22float2(hp[1]);
                v = make_float4(f01.x * inv, f01.y * inv, f23.x * inv, f23.y * inv);
            }
            ar[2*i]   = pack2h(v.x, v.y);
            ar[2*i+1] = pack2h(v.z, v.w);
        }
    };
    auto stsA = [&](uint32_t abuf, const uint32_t (&ar)[8]) {
        uint32_t base = abuf + (uint32_t)gr_ * ASTR1 + (uint32_t)kk0 * 2;
#pragma unroll
        for (int i = 0; i < 4; i++)
            STSV2(base + i * 8, ar[2*i], ar[2*i+1]);
    };

    float acc[2][8][4];
    CLR_ACC();
    const int rb = m0 + (lane >> 2);
    const int cb = n0w + (lane & 3) * 2;

    // -------- L1: 2 chunks --------
    {
        uint32_t ar[8];
        gather(0, ar); stsA(sb + OFF_A10, ar);
        cp_chunk(sb + OFF_BB0, g_mw1, 0, tid); CP_COMMIT();
    }
    for (int c = 0; c < 2; ++c) {
        uint32_t ar[8];
        if (c + 1 < 2) gather(c + 1, ar);
        CP_WAIT0();
        __syncthreads();
        if (c + 1 < 2) { cp_chunk(sb + OFF_BB1, g_mw1, 1, tid); CP_COMMIT(); }
        mma_chunk(acc, sb + ((c & 1) ? OFF_A11 : OFF_A10), ASTR1,
                  sb + ((c & 1) ? OFF_BB1 : OFF_BB0), lane, m0, n0w);
        if (c + 1 < 2) stsA(sb + OFF_A11, ar);
    }
    __syncthreads();   // all A1 reads done before epi1 writes A2 (aliased)
    cp_chunk(sb + OFF_BB0, g_mw2, 0, tid); CP_COMMIT();   // L2 chunk0 -> BB0

    // epi1: + pf*wfr + b1 -> softplus -> A2 (fp16)
    {
        float pf[4];
#pragma unroll
        for (int q = 0; q < 4; q++)
            pf[q] = pfs[rb + (q >> 1) * 16 + (q & 1) * 8];
#pragma unroll
        for (int mi = 0; mi < 2; mi++)
#pragma unroll
            for (int ni = 0; ni < 8; ni++) {
                int col = cb + ni * 8;
                float2 bb = *(float2*)&bias1s[col];
                float2 wf = *(float2*)&wfr[col];
                int row = rb + mi * 16;
                uint32_t ad = sb + OFF_A2 + (uint32_t)row * ASTR2 + (uint32_t)col * 2;
                STS32(ad, pack2h(sp(acc[mi][ni][0] + pf[mi*2]*wf.x + bb.x),
                                 sp(acc[mi][ni][1] + pf[mi*2]*wf.y + bb.y)));
                STS32(ad + 8*ASTR2, pack2h(sp(acc[mi][ni][2] + pf[mi*2+1]*wf.x + bb.x),
                                           sp(acc[mi][ni][3] + pf[mi*2+1]*wf.y + bb.y)));
            }
    }
    CLR_ACC();

    // -------- L2: 4 chunks (cur = c&1 ? BB1 : BB0) --------
    for (int c = 0; c < 4; ++c) {
        CP_WAIT0();
        __syncthreads();
        if (c + 1 < 4) { cp_chunk(sb + (((c+1)&1)?OFF_BB1:OFF_BB0), g_mw2, c+1, tid); CP_COMMIT(); }
        else           { cp_chunk(sb + OFF_BB0, g_gwc, 0, tid); CP_COMMIT(); }  // c=3 cur=BB1, BB0 free
        mma_chunk(acc, sb + OFF_A2 + (uint32_t)c * 128, ASTR2,
                  sb + ((c&1)?OFF_BB1:OFF_BB0), lane, m0, n0w);
    }
    __syncthreads();   // all A2 reads done before epi2 rewrites A2

    // epi2 -> ctx fp16 in A2
#pragma unroll
    for (int mi = 0; mi < 2; mi++)
#pragma unroll
        for (int ni = 0; ni < 8; ni++) {
            int col = cb + ni * 8;
            float2 bb = *(float2*)&bias2s[col];
            int row = rb + mi * 16;
            uint32_t ad = sb + OFF_A2 + (uint32_t)row * ASTR2 + (uint32_t)col * 2;
            STS32(ad, pack2h(sp(acc[mi][ni][0]+bb.x), sp(acc[mi][ni][1]+bb.y)));
            STS32(ad + 8*ASTR2, pack2h(sp(acc[mi][ni][2]+bb.x), sp(acc[mi][ni][3]+bb.y)));
        }
    CLR_ACC();

    // -------- L3: 4 chunks (cur = c&1 ? BB1 : BB0; chunk0 in BB0) --------
    for (int c = 0; c < 4; ++c) {
        CP_WAIT0();
        __syncthreads();
        if (c + 1 < 4) { cp_chunk(sb + (((c+1)&1)?OFF_BB1:OFF_BB0), g_gwc, c+1, tid); CP_COMMIT(); }
        mma_chunk(acc, sb + OFF_A2 + (uint32_t)c * 128, ASTR2,
                  sb + ((c&1)?OFF_BB1:OFF_BB0), lane, m0, n0w);
    }

    // epi3 -> g_ctxpre (fp16)
#pragma unroll
    for (int mi = 0; mi < 2; mi++)
#pragma unroll
        for (int ni = 0; ni < 8; ni++) {
            int col = cb + ni * 8;
            int gr = rowBase + rb + mi * 16;
            if (gr < M_SEG)
                *(uint32_t*)&g_ctxpre[(size_t)gr * 256 + col] =
                    pack2h(acc[mi][ni][0], acc[mi][ni][1]);
            if (gr + 8 < M_SEG)
                *(uint32_t*)&g_ctxpre[(size_t)(gr+8) * 256 + col] =
                    pack2h(acc[mi][ni][2], acc[mi][ni][3]);
        }
}

// ---------------------------------------------------------------------------
// gate: emb L1 (2 chunks, single B buf) + ctxpre tile prefetched into BB1
//       + frac*w128 epi -> L2 (4) -> out.  Tile 64x256, 2 CTAs/SM.
__global__ __launch_bounds__(256, 2)
void k_gate(const float* __restrict__ emb, const float* __restrict__ frac,
            const int* __restrict__ seg, const float* __restrict__ gW1,
            const float* __restrict__ b1v, const float* __restrict__ b2v,
            float* __restrict__ outp) {
    extern __shared__ __align__(16) char sm[];
    const uint32_t sb = smem_u32(sm);
    const int tid = threadIdx.x, w = tid >> 5, lane = tid & 31;
    const int m0 = (w & 1) * 32, n0w = (w >> 1) * 64;
    const int rowBase = blockIdx.x * 64;

    float* bias1s = (float*)(sm + OFF_B1S);
    float* bias2s = (float*)(sm + OFF_B2S);
    float* fracs  = (float*)(sm + OFF_FRS);
    float* wfrac  = (float*)(sm + OFF_WFR);

    bias1s[tid] = b1v[tid];
    bias2s[tid] = b2v[tid];
    wfrac[tid]  = gW1[128 * 256 + tid];
    if (tid < 64) fracs[tid] = frac[rowBase + tid];

    const int gr_ = tid >> 2, gq = tid & 3;
    const long long rg = rowBase + gr_;
    const int kk0 = gq * 16;
    auto gatherE = [&](int c, uint32_t (&ar)[8]) {
#pragma unroll
        for (int i = 0; i < 4; i++) {
            float4 v = *(const float4*)&emb[rg * EMB + c * 64 + kk0 + i * 4];
            ar[2*i]   = pack2h(v.x, v.y);
            ar[2*i+1] = pack2h(v.z, v.w);
        }
    };
    auto stsA = [&](uint32_t abuf, const uint32_t (&ar)[8]) {
        uint32_t base = abuf + (uint32_t)gr_ * ASTR1 + (uint32_t)kk0 * 2;
#pragma unroll
        for (int i = 0; i < 4; i++)
            STSV2(base + i * 8, ar[2*i], ar[2*i+1]);
    };

    float acc[2][8][4];
    CLR_ACC();
    const int rb = m0 + (lane >> 2);
    const int cb = n0w + (lane & 3) * 2;

    // -------- prologue: issue B c0 (G0) and ctxpre tile (G1) --------
    cp_chunk(sb + OFF_BB0, g_gwe, 0, tid); CP_COMMIT();      // G0
    {   // ctxpre prefetch: thread t -> row t>>2 (quarter t&3), 8 x 16B
        int s = seg[rowBase + gr_];
        const uint4* src = (const uint4*)&g_ctxpre[(size_t)s * 256 + gq * 64];
        uint32_t dst = sb + OFF_BB1 + (uint32_t)gr_ * CXSTR + (uint32_t)gq * 128;
#pragma unroll
        for (int i = 0; i < 8; i++) CP16(dst + i * 16, src + i);
    }
    CP_COMMIT();                                             // G1
    {
        uint32_t ar[8];
        gatherE(0, ar); stsA(sb + OFF_A10, ar);
        gatherE(1, ar); stsA(sb + OFF_A11, ar);
    }

    // -------- L1 chunk 0 --------
    CP_WAIT1();            // G0 done (G1 may be in flight)
    __syncthreads();       // A10 + BB0 visible; smem preamble visible
    mma_chunk(acc, sb + OFF_A10, ASTR1, sb + OFF_BB0, lane, m0, n0w);
    __syncthreads();       // all warps done reading BB0
    cp_chunk(sb + OFF_BB0, g_gwe, 1, tid); CP_COMMIT();      // G2: B c1 -> BB0

    // -------- L1 chunk 1 --------
    CP_WAIT0();            // G1 (ctxpre) + G2 done
    __syncthreads();
    mma_chunk(acc, sb + OFF_A11, ASTR1, sb + OFF_BB0, lane, m0, n0w);
    __syncthreads();       // A1 reads done before epi1 writes A2 (aliased)
    cp_chunk(sb + OFF_BB0, g_gw2, 0, tid); CP_COMMIT();      // G3: L2 c0 -> BB0

    // epi1: acc += ctx(smem) + frac*wfrac + b1 -> softplus -> A2
    {
        float fr[4];
#pragma unroll
        for (int q = 0; q < 4; q++)
            fr[q] = fracs[rb + (q >> 1) * 16 + (q & 1) * 8];
#pragma unroll
        for (int mi = 0; mi < 2; mi++)
#pragma unroll
            for (int ni = 0; ni < 8; ni++) {
                int col = cb + ni * 8;
                float2 bb = *(float2*)&bias1s[col];
                float2 wf = *(float2*)&wfrac[col];
                int row = rb + mi * 16;
                uint32_t cxa = sb + OFF_BB1 + (uint32_t)row * CXSTR + (uint32_t)col * 2;
                float2 c0 = lds_h2f(cxa);
                float2 c1 = lds_h2f(cxa + 8 * CXSTR);
                uint32_t ad = sb + OFF_A2 + (uint32_t)row * ASTR2 + (uint32_t)col * 2;
                STS32(ad, pack2h(sp(acc[mi][ni][0] + c0.x + fr[mi*2]*wf.x + bb.x),
                                 sp(acc[mi][ni][1] + c0.y + fr[mi*2]*wf.y + bb.y)));
                STS32(ad + 8*ASTR2, pack2h(sp(acc[mi][ni][2] + c1.x + fr[mi*2+1]*wf.x + bb.x),
                                           sp(acc[mi][ni][3] + c1.y + fr[mi*2+1]*wf.y + bb.y)));
            }
    }
    CLR_ACC();

    // -------- L2: 4 chunks (cur = c&1 ? BB1 : BB0) --------
    for (int c = 0; c < 4; ++c) {
        CP_WAIT0();
        __syncthreads();   // iter0: epi1 A2 writes + BB1 ctx reads complete
        if (c + 1 < 4) { cp_chunk(sb + (((c+1)&1)?OFF_BB1:OFF_BB0), g_gw2, c+1, tid); CP_COMMIT(); }
        mma_chunk(acc, sb + OFF_A2 + (uint32_t)c * 128, ASTR2,
                  sb + ((c&1)?OFF_BB1:OFF_BB0), lane, m0, n0w);
    }

    // epi2 -> out
#pragma unroll
    for (int mi = 0; mi < 2; mi++)
#pragma unroll
        for (int ni = 0; ni < 8; ni++) {
            int col = cb + ni * 8;
            float2 bb = *(float2*)&bias2s[col];
            int gr = rowBase + rb + mi * 16;
            *(float2*)&outp[(long long)gr * 256 + col] =
                make_float2(sp(acc[mi][ni][0]+bb.x), sp(acc[mi][ni][1]+bb.y));
            *(float2*)&outp[(long long)(gr+8) * 256 + col] =
                make_float2(sp(acc[mi][ni][2]+bb.x), sp(acc[mi][ni][3]+bb.y));
        }
}

// ---------------------------------------------------------------------------
extern "C" void kernel_launch(void* const* d_in, const int* in_sizes, int n_in,
                              void* d_out, int out_size) {
    const float* emb  = (const float*)d_in[0];
    const float* frac = (const float*)d_in[1];
    const int*   seg  = (const int*)  d_in[2];
    const float* iW1  = (const float*)d_in[3];
    const float* ib1  = (const float*)d_in[4];
    const float* iW2  = (const float*)d_in[5];
    const float* ib2  = (const float*)d_in[6];
    const float* gW1  = (const float*)d_in[7];
    const float* gb1  = (const float*)d_in[8];
    const float* gW2  = (const float*)d_in[9];
    const float* gb2  = (const float*)d_in[10];
    float* out = (float*)d_out;

    cudaFuncSetAttribute(k_mix,  cudaFuncAttributeMaxDynamicSharedMemorySize, SMEM_TOTAL);
    cudaFuncSetAttribute(k_gate, cudaFuncAttributeMaxDynamicSharedMemorySize, SMEM_TOTAL);

    // launch 1: merged prep + zero
    long long totz = (long long)M_SEG * PHSTR / 2 + M_SEG;
    long long totp = 16LL * CHW;
    long long tot1 = totz > totp ? totz : totp;
    k_prepzero<<<(unsigned)((tot1 + 255) / 256), 256>>>(gW1, gW2, iW1, iW2);

    // launch 2: segment accumulate
    float* out_frac = nullptr;
    if ((long long)out_size >= (long long)N_ROWS * (LAT + 1))
        out_frac = out + (size_t)N_ROWS * LAT;
    long long tota = (long long)N_ROWS * 17;
    k_accum<<<(unsigned)((tota + 255) / 256), 256>>>(emb, frac, seg, out_frac);

    // launch 3: mixture MLP (+ hoisted ctx GEMM)
    k_mix<<<(M_SEG + 63)/64, 256, SMEM_TOTAL>>>(iW1, ib1, ib2);

    // launch 4: gate MLP
    k_gate<<<N_ROWS / 64, 256, SMEM_TOTAL>>>(emb, frac, seg, gW1, gb1, gb2, out);
}